// round 7
// baseline (speedup 1.0000x reference)
#include <cuda_runtime.h>
#include <cuda_bf16.h>

typedef unsigned long long ull;
union F2 { float2 f; ull u; };
#define FMA2(c,a,b) asm("fma.rn.f32x2 %0, %1, %2, %0;" : "+l"(c) : "l"(a), "l"(b))

#define Bb 64
#define Tt 512
#define Hh 1024
#define G4 4096
#define HSEQ_N (Bb*Tt*Hh)

// scratch (device globals: allocation-free rule)
__device__ float g_xp[(size_t)Bb * Tt * G4];   // 512 MB x_proj
__device__ float g_h[2][Bb * Hh];              // double-buffered h
__device__ unsigned g_bar_count;
__device__ unsigned g_bar_gen;

// ===========================================================================
// Phase 1: g_xp[M=32768, 4096] = input[M,1024] @ Wi^T + b
// Tile 128x64x16, 256 threads, 32 outputs/thread, packed f32x2 FMA.
// Staging reordered: LDG next chunk -> compute -> STS next chunk.
// ===========================================================================
#define PM 128
#define PN 64
#define PK 16

__global__ __launch_bounds__(256, 2) void xproj_kernel(
    const float* __restrict__ A,
    const float* __restrict__ W0, const float* __restrict__ W1,
    const float* __restrict__ W2, const float* __restrict__ W3,
    const float* __restrict__ b0, const float* __restrict__ b1,
    const float* __restrict__ b2, const float* __restrict__ b3)
{
    __shared__ __align__(16) ull as_[2][PK][PM / 2];  // (A[2m],A[2m+1]) row pairs
    __shared__ __align__(16) ull bs_[2][PK][PN];      // (w,w) duplicated

    const int tid = threadIdx.x;
    const int nTile = blockIdx.x & 63;
    const int mTile = blockIdx.x >> 6;
    const int m0 = mTile * PM;
    const int n0 = nTile * PN;
    const int q = n0 >> 10;
    const float* W  = (q == 0) ? W0 : (q == 1) ? W1 : (q == 2) ? W2 : W3;
    const float* bb = (q == 0) ? b0 : (q == 1) ? b1 : (q == 2) ? b2 : b3;
    const int nq = n0 & 1023;

    const int ar = tid >> 1, ak = (tid & 1) * 8;
    const int wr = tid >> 2, wk = (tid & 3) * 4;
    const int tn = tid & 15, tm = tid >> 4;

    ull acc[4][4];
    #pragma unroll
    for (int i = 0; i < 4; i++)
        #pragma unroll
        for (int j = 0; j < 4; j++) acc[i][j] = 0ull;

    const float* Arow = A + (size_t)(m0 + ar) * 1024;
    const float* Wrow = W + (size_t)(nq + wr) * 1024;
    const int mp = ar >> 1, hl = ar & 1;

    {   // stage chunk 0
        float4 v0 = *(const float4*)(Arow + ak);
        float4 v1 = *(const float4*)(Arow + ak + 4);
        float4 w  = *(const float4*)(Wrow + wk);
        #pragma unroll
        for (int i = 0; i < 4; i++) {
            ((float*)&as_[0][ak + i][mp])[hl]     = (&v0.x)[i];
            ((float*)&as_[0][ak + 4 + i][mp])[hl] = (&v1.x)[i];
            F2 t; t.f = make_float2((&w.x)[i], (&w.x)[i]);
            bs_[0][wk + i][wr] = t.u;
        }
    }
    __syncthreads();

    int buf = 0;
    for (int ch = 0; ch < 64; ch++) {
        float4 v0, v1, w;
        const bool has = (ch < 63);
        if (has) {
            const int k0 = (ch + 1) * PK;
            v0 = *(const float4*)(Arow + k0 + ak);
            v1 = *(const float4*)(Arow + k0 + ak + 4);
            w  = *(const float4*)(Wrow + k0 + wk);
        }
        #pragma unroll
        for (int kk = 0; kk < PK; kk++) {
            ulonglong2 a0 = *(const ulonglong2*)&as_[buf][kk][4 * tm];
            ulonglong2 a1 = *(const ulonglong2*)&as_[buf][kk][4 * tm + 2];
            ulonglong2 c0 = *(const ulonglong2*)&bs_[buf][kk][4 * tn];
            ulonglong2 c1 = *(const ulonglong2*)&bs_[buf][kk][4 * tn + 2];
            FMA2(acc[0][0], a0.x, c0.x); FMA2(acc[0][1], a0.x, c0.y);
            FMA2(acc[0][2], a0.x, c1.x); FMA2(acc[0][3], a0.x, c1.y);
            FMA2(acc[1][0], a0.y, c0.x); FMA2(acc[1][1], a0.y, c0.y);
            FMA2(acc[1][2], a0.y, c1.x); FMA2(acc[1][3], a0.y, c1.y);
            FMA2(acc[2][0], a1.x, c0.x); FMA2(acc[2][1], a1.x, c0.y);
            FMA2(acc[2][2], a1.x, c1.x); FMA2(acc[2][3], a1.x, c1.y);
            FMA2(acc[3][0], a1.y, c0.x); FMA2(acc[3][1], a1.y, c0.y);
            FMA2(acc[3][2], a1.y, c1.x); FMA2(acc[3][3], a1.y, c1.y);
        }
        if (has) {
            const int nb = buf ^ 1;
            #pragma unroll
            for (int i = 0; i < 4; i++) {
                ((float*)&as_[nb][ak + i][mp])[hl]     = (&v0.x)[i];
                ((float*)&as_[nb][ak + 4 + i][mp])[hl] = (&v1.x)[i];
                F2 t; t.f = make_float2((&w.x)[i], (&w.x)[i]);
                bs_[nb][wk + i][wr] = t.u;
            }
        }
        __syncthreads();
        buf ^= 1;
    }

    float4 bv = *(const float4*)(bb + nq + 4 * tn);
    #pragma unroll
    for (int i = 0; i < 4; i++) {
        F2 u0, u1, u2, u3;
        u0.u = acc[i][0]; u1.u = acc[i][1]; u2.u = acc[i][2]; u3.u = acc[i][3];
        const int mA = m0 + (4 * tm + i) * 2;
        float4 r0 = make_float4(u0.f.x + bv.x, u1.f.x + bv.y, u2.f.x + bv.z, u3.f.x + bv.w);
        float4 r1 = make_float4(u0.f.y + bv.x, u1.f.y + bv.y, u2.f.y + bv.z, u3.f.y + bv.w);
        *(float4*)(g_xp + (size_t)mA * G4 + n0 + 4 * tn)       = r0;
        *(float4*)(g_xp + (size_t)(mA + 1) * G4 + n0 + 4 * tn) = r1;
    }
}

// ===========================================================================
// Phase 2: persistent scan. 128 CTAs x 512 thr (16 warps).
// CTA owns 32 gate-rows (8 hidden x 4 gates); Wh slice SMEM-resident as
// k-pair f32x2 for all 512 steps.
// Warp w: rg = w&3 (8 rows, warp-uniform -> w-loads broadcast), bset = w>>2.
// Lane: sl = lane&7 (k-slice), bq = lane>>3 -> batches B0 = bset*16+bq*4 (+0..3).
// Per thread: 4 batches x 8 rows = 32 f2 accumulators, shuffle-reduced over sl.
// ===========================================================================
#define WSR 34
#define HDR 66
#define SM_WS (512 * WSR * 8)       // 139264
#define SM_HD (2 * 64 * HDR * 8)    // 67584
#define SM_GB (64 * 33 * 4)         // 8448
#define SM_SCAN (SM_WS + SM_HD + SM_GB)

__device__ __forceinline__ float sigf(float x) { return 1.0f / (1.0f + __expf(-x)); }

__global__ __launch_bounds__(512, 1) void lstm_scan(
    const float* __restrict__ h0, const float* __restrict__ c0,
    const float* __restrict__ Whi, const float* __restrict__ Whf,
    const float* __restrict__ Whg, const float* __restrict__ Who,
    float* __restrict__ out)
{
    extern __shared__ char sm[];
    ull*   ws = (ull*)sm;                      // [512 kp][WSR]: (w[r][2kp],w[r][2kp+1]) at [kp*WSR+r]
    ull*   hd = (ull*)(sm + SM_WS);            // [2][64 b][HDR]: (h[b][2kp],h[b][2kp+1])
    float* gb = (float*)(sm + SM_WS + SM_HD);  // [64][33] gate preacts

    const int tid  = threadIdx.x;
    const int j0   = blockIdx.x * 8;
    const int w    = tid >> 5;
    const int lane = tid & 31;
    const int sl   = lane & 7;
    const int bq   = lane >> 3;
    const int rg   = w & 3;          // warp-uniform gate/row-group
    const int bset = w >> 2;
    const int B0   = bset * 16 + bq * 4;

    // one-time: pack this CTA's 32 Wh rows into SMEM (row r = gate*8 + jl)
    const float* Wm[4] = {Whi, Whf, Whg, Who};
    for (int r = 0; r < 32; r++) {
        const float* src = Wm[r >> 3] + (size_t)(j0 + (r & 7)) * Hh;
        for (int kp = tid; kp < 512; kp += 512) {
            F2 tt; tt.f = *(const float2*)(src + 2 * kp);
            ws[kp * WSR + r] = tt.u;
        }
    }

    const int rb = tid >> 3, rj = tid & 7;     // gate-phase: 1 cell per thread
    float creg = c0[rb * Hh + j0 + rj];
    __syncthreads();

    for (int t = 0; t < Tt; t++) {
        const float* hcur = (t == 0) ? h0 : g_h[t & 1];
        float* hnxt = g_h[(t + 1) & 1];

        // prefetch x_proj contributions (hidden under mainloop)
        float xq0, xq1, xq2, xq3;
        {
            const float* xb = g_xp + ((size_t)rb * Tt + t) * G4 + j0 + rj;
            xq0 = xb[0]; xq1 = xb[Hh]; xq2 = xb[2 * Hh]; xq3 = xb[3 * Hh];
        }

        ull acc[4][8];
        #pragma unroll
        for (int j = 0; j < 4; j++)
            #pragma unroll
            for (int r = 0; r < 8; r++) acc[j][r] = 0ull;

        // stage chunk 0 (k 0..127): 512 thr x 4 float4, conflict-free STS.128
        #pragma unroll
        for (int it = 0; it < 4; it++) {
            int idx = it * 512 + tid;
            int b = idx >> 5, k4 = idx & 31;
            float4 v = *(const float4*)(hcur + b * Hh + k4 * 4);
            F2 t0, t1; t0.f = make_float2(v.x, v.y); t1.f = make_float2(v.z, v.w);
            ulonglong2 w2; w2.x = t0.u; w2.y = t1.u;
            *(ulonglong2*)(hd + b * HDR + k4 * 2) = w2;
        }
        __syncthreads();

        int buf = 0;
        for (int ch = 0; ch < 8; ch++) {
            float4 pre0, pre1, pre2, pre3;
            const bool has = (ch < 7);
            if (has) {                  // LDG next chunk first (hide latency)
                const float* hsrc = hcur + (ch + 1) * 128;
                int i0 = tid;             pre0 = *(const float4*)(hsrc + (i0 >> 5) * Hh + (i0 & 31) * 4);
                int i1 = 512 + tid;       pre1 = *(const float4*)(hsrc + (i1 >> 5) * Hh + (i1 & 31) * 4);
                int i2 = 1024 + tid;      pre2 = *(const float4*)(hsrc + (i2 >> 5) * Hh + (i2 & 31) * 4);
                int i3 = 1536 + tid;      pre3 = *(const float4*)(hsrc + (i3 >> 5) * Hh + (i3 & 31) * 4);
            }
            const ull* hb = hd + (size_t)buf * 64 * HDR;
            const ull* wchunk = ws + (size_t)(ch * 64) * WSR + rg * 8;
            #pragma unroll
            for (int i = 0; i < 8; i++) {
                const int kl = i * 8 + sl;
                const ull* wp = wchunk + (size_t)kl * WSR;
                ulonglong2 wA = *(const ulonglong2*)(wp);
                ulonglong2 wB = *(const ulonglong2*)(wp + 2);
                ulonglong2 wC = *(const ulonglong2*)(wp + 4);
                ulonglong2 wD = *(const ulonglong2*)(wp + 6);
                ull hv0 = hb[(B0 + 0) * HDR + kl];
                ull hv1 = hb[(B0 + 1) * HDR + kl];
                ull hv2 = hb[(B0 + 2) * HDR + kl];
                ull hv3 = hb[(B0 + 3) * HDR + kl];
                FMA2(acc[0][0], hv0, wA.x); FMA2(acc[0][1], hv0, wA.y);
                FMA2(acc[0][2], hv0, wB.x); FMA2(acc[0][3], hv0, wB.y);
                FMA2(acc[0][4], hv0, wC.x); FMA2(acc[0][5], hv0, wC.y);
                FMA2(acc[0][6], hv0, wD.x); FMA2(acc[0][7], hv0, wD.y);
                FMA2(acc[1][0], hv1, wA.x); FMA2(acc[1][1], hv1, wA.y);
                FMA2(acc[1][2], hv1, wB.x); FMA2(acc[1][3], hv1, wB.y);
                FMA2(acc[1][4], hv1, wC.x); FMA2(acc[1][5], hv1, wC.y);
                FMA2(acc[1][6], hv1, wD.x); FMA2(acc[1][7], hv1, wD.y);
                FMA2(acc[2][0], hv2, wA.x); FMA2(acc[2][1], hv2, wA.y);
                FMA2(acc[2][2], hv2, wB.x); FMA2(acc[2][3], hv2, wB.y);
                FMA2(acc[2][4], hv2, wC.x); FMA2(acc[2][5], hv2, wC.y);
                FMA2(acc[2][6], hv2, wD.x); FMA2(acc[2][7], hv2, wD.y);
                FMA2(acc[3][0], hv3, wA.x); FMA2(acc[3][1], hv3, wA.y);
                FMA2(acc[3][2], hv3, wB.x); FMA2(acc[3][3], hv3, wB.y);
                FMA2(acc[3][4], hv3, wC.x); FMA2(acc[3][5], hv3, wC.y);
                FMA2(acc[3][6], hv3, wD.x); FMA2(acc[3][7], hv3, wD.y);
            }
            if (has) {                  // STS next chunk after compute
                const int nb = buf ^ 1;
                ull* hdn = hd + (size_t)nb * 64 * HDR;
                F2 t0, t1; ulonglong2 w2;
                int i0 = tid;
                t0.f = make_float2(pre0.x, pre0.y); t1.f = make_float2(pre0.z, pre0.w);
                w2.x = t0.u; w2.y = t1.u;
                *(ulonglong2*)(hdn + (i0 >> 5) * HDR + (i0 & 31) * 2) = w2;
                int i1 = 512 + tid;
                t0.f = make_float2(pre1.x, pre1.y); t1.f = make_float2(pre1.z, pre1.w);
                w2.x = t0.u; w2.y = t1.u;
                *(ulonglong2*)(hdn + (i1 >> 5) * HDR + (i1 & 31) * 2) = w2;
                int i2 = 1024 + tid;
                t0.f = make_float2(pre2.x, pre2.y); t1.f = make_float2(pre2.z, pre2.w);
                w2.x = t0.u; w2.y = t1.u;
                *(ulonglong2*)(hdn + (i2 >> 5) * HDR + (i2 & 31) * 2) = w2;
                int i3 = 1536 + tid;
                t0.f = make_float2(pre3.x, pre3.y); t1.f = make_float2(pre3.z, pre3.w);
                w2.x = t0.u; w2.y = t1.u;
                *(ulonglong2*)(hdn + (i3 >> 5) * HDR + (i3 & 31) * 2) = w2;
            }
            __syncthreads();
            buf ^= 1;
        }

        // reduce 8 k-slices (xor over lane bits 0..2) + pair halves; sl==0 publishes
        #pragma unroll
        for (int j = 0; j < 4; j++)
            #pragma unroll
            for (int r = 0; r < 8; r++) {
                F2 u; u.u = acc[j][r];
                float v = u.f.x + u.f.y;
                v += __shfl_xor_sync(0xffffffffu, v, 1);
                v += __shfl_xor_sync(0xffffffffu, v, 2);
                v += __shfl_xor_sync(0xffffffffu, v, 4);
                if (sl == 0) gb[(B0 + j) * 33 + rg * 8 + r] = v;
            }
        __syncthreads();

        // gates + state update: one (b, j) cell per thread
        {
            const float* gr = gb + rb * 33;
            float gi = gr[rj]      + xq0;
            float gf = gr[8 + rj]  + xq1;
            float gg = gr[16 + rj] + xq2;
            float go = gr[24 + rj] + xq3;
            float iv = sigf(gi), fv = sigf(gf), ov = sigf(go);
            float gv = 2.0f * sigf(2.0f * gg) - 1.0f;
            creg = fv * creg + iv * gv;
            float hv = ov * (2.0f * sigf(2.0f * creg) - 1.0f);
            hnxt[rb * Hh + j0 + rj] = hv;
            out[((size_t)rb * Tt + t) * Hh + j0 + rj] = hv;
            if (t == Tt - 1) {
                out[HSEQ_N + rb * Hh + j0 + rj] = hv;
                out[HSEQ_N + Bb * Hh + rb * Hh + j0 + rj] = creg;
            }
        }

        if (t < Tt - 1) {                       // grid barrier
            __syncthreads();
            if (tid == 0) {
                __threadfence();                 // drain h stores (gpu scope)
                unsigned g = *(volatile unsigned*)&g_bar_gen;
                if (atomicAdd(&g_bar_count, 1u) == gridDim.x - 1u) {
                    atomicExch(&g_bar_count, 0u);
                    __threadfence();
                    atomicAdd(&g_bar_gen, 1u);
                } else {
                    while (*(volatile unsigned*)&g_bar_gen == g) __nanosleep(64);
                }
                __threadfence();                 // acquire before reading new h
            }
            __syncthreads();
        }
    }
}

// ===========================================================================
extern "C" void kernel_launch(void* const* d_in, const int* in_sizes, int n_in,
                              void* d_out, int out_size)
{
    (void)in_sizes; (void)n_in; (void)out_size;
    const float* x   = (const float*)d_in[0];
    const float* h0  = (const float*)d_in[1];
    const float* c0  = (const float*)d_in[2];
    const float* Wii = (const float*)d_in[3];
    const float* Whi = (const float*)d_in[4];
    const float* bi  = (const float*)d_in[5];
    const float* Wif = (const float*)d_in[6];
    const float* Whf = (const float*)d_in[7];
    const float* bf  = (const float*)d_in[8];
    const float* Wig = (const float*)d_in[9];
    const float* Whg = (const float*)d_in[10];
    const float* bg_ = (const float*)d_in[11];
    const float* Wio = (const float*)d_in[12];
    const float* Who = (const float*)d_in[13];
    const float* bo  = (const float*)d_in[14];
    float* out = (float*)d_out;

    xproj_kernel<<<16384, 256>>>(x, Wii, Wif, Wig, Wio, bi, bf, bg_, bo);

    static int attr_done = 0;
    if (!attr_done) {
        cudaFuncSetAttribute(lstm_scan,
                             cudaFuncAttributeMaxDynamicSharedMemorySize, SM_SCAN);
        attr_done = 1;
    }
    lstm_scan<<<128, 512, SM_SCAN>>>(h0, c0, Whi, Whf, Whg, Who, out);
}

// round 8
// speedup vs baseline: 1.3991x; 1.3991x over previous
#include <cuda_runtime.h>
#include <cuda_bf16.h>

typedef unsigned long long ull;
union F2 { float2 f; ull u; };
#define FMA2(c,a,b) asm("fma.rn.f32x2 %0, %1, %2, %0;" : "+l"(c) : "l"(a), "l"(b))

#define Bb 64
#define Tt 512
#define Hh 1024
#define G4 4096
#define HSEQ_N (Bb*Tt*Hh)

// scratch (device globals: allocation-free rule)
__device__ float g_xp[(size_t)Bb * Tt * G4];   // 512 MB x_proj
__device__ float g_h[2][Bb * Hh];              // double-buffered h
__device__ unsigned g_bar_count;
__device__ unsigned g_bar_gen;

// ===========================================================================
// Phase 1: g_xp[M=32768, 4096] = input[M,1024] @ Wi^T + b
// Tile 128x64x16, 256 threads, 32 outputs/thread, packed f32x2 FMA.
// R5 staging order (transients dead before compute) + forced 2 CTAs/SM.
// ===========================================================================
#define PM 128
#define PN 64
#define PK 16

__global__ __launch_bounds__(256, 2) void xproj_kernel(
    const float* __restrict__ A,
    const float* __restrict__ W0, const float* __restrict__ W1,
    const float* __restrict__ W2, const float* __restrict__ W3,
    const float* __restrict__ b0, const float* __restrict__ b1,
    const float* __restrict__ b2, const float* __restrict__ b3)
{
    __shared__ __align__(16) ull as_[2][PK][PM / 2];  // (A[2m],A[2m+1]) row pairs
    __shared__ __align__(16) ull bs_[2][PK][PN];      // (w,w) duplicated

    const int tid = threadIdx.x;
    const int nTile = blockIdx.x & 63;
    const int mTile = blockIdx.x >> 6;
    const int m0 = mTile * PM;
    const int n0 = nTile * PN;
    const int q = n0 >> 10;
    const float* W  = (q == 0) ? W0 : (q == 1) ? W1 : (q == 2) ? W2 : W3;
    const float* bb = (q == 0) ? b0 : (q == 1) ? b1 : (q == 2) ? b2 : b3;
    const int nq = n0 & 1023;

    const int ar = tid >> 1, ak = (tid & 1) * 8;
    const int wr = tid >> 2, wk = (tid & 3) * 4;
    const int tn = tid & 15, tm = tid >> 4;

    ull acc[4][4];
    #pragma unroll
    for (int i = 0; i < 4; i++)
        #pragma unroll
        for (int j = 0; j < 4; j++) acc[i][j] = 0ull;

    const float* Arow = A + (size_t)(m0 + ar) * 1024;
    const float* Wrow = W + (size_t)(nq + wr) * 1024;
    const int mp = ar >> 1, hl = ar & 1;

    {   // stage chunk 0
        float4 v0 = *(const float4*)(Arow + ak);
        float4 v1 = *(const float4*)(Arow + ak + 4);
        float4 w  = *(const float4*)(Wrow + wk);
        #pragma unroll
        for (int i = 0; i < 4; i++) {
            ((float*)&as_[0][ak + i][mp])[hl]     = (&v0.x)[i];
            ((float*)&as_[0][ak + 4 + i][mp])[hl] = (&v1.x)[i];
            F2 t; t.f = make_float2((&w.x)[i], (&w.x)[i]);
            bs_[0][wk + i][wr] = t.u;
        }
    }
    __syncthreads();

    int buf = 0;
    for (int ch = 0; ch < 64; ch++) {
        if (ch < 63) {                      // stage next chunk, then compute
            const int k0 = (ch + 1) * PK;
            const int nb = buf ^ 1;
            float4 v0 = *(const float4*)(Arow + k0 + ak);
            float4 v1 = *(const float4*)(Arow + k0 + ak + 4);
            float4 w  = *(const float4*)(Wrow + k0 + wk);
            #pragma unroll
            for (int i = 0; i < 4; i++) {
                ((float*)&as_[nb][ak + i][mp])[hl]     = (&v0.x)[i];
                ((float*)&as_[nb][ak + 4 + i][mp])[hl] = (&v1.x)[i];
                F2 t; t.f = make_float2((&w.x)[i], (&w.x)[i]);
                bs_[nb][wk + i][wr] = t.u;
            }
        }
        #pragma unroll
        for (int kk = 0; kk < PK; kk++) {
            ulonglong2 a0 = *(const ulonglong2*)&as_[buf][kk][4 * tm];
            ulonglong2 a1 = *(const ulonglong2*)&as_[buf][kk][4 * tm + 2];
            ulonglong2 c0 = *(const ulonglong2*)&bs_[buf][kk][4 * tn];
            ulonglong2 c1 = *(const ulonglong2*)&bs_[buf][kk][4 * tn + 2];
            FMA2(acc[0][0], a0.x, c0.x); FMA2(acc[0][1], a0.x, c0.y);
            FMA2(acc[0][2], a0.x, c1.x); FMA2(acc[0][3], a0.x, c1.y);
            FMA2(acc[1][0], a0.y, c0.x); FMA2(acc[1][1], a0.y, c0.y);
            FMA2(acc[1][2], a0.y, c1.x); FMA2(acc[1][3], a0.y, c1.y);
            FMA2(acc[2][0], a1.x, c0.x); FMA2(acc[2][1], a1.x, c0.y);
            FMA2(acc[2][2], a1.x, c1.x); FMA2(acc[2][3], a1.x, c1.y);
            FMA2(acc[3][0], a1.y, c0.x); FMA2(acc[3][1], a1.y, c0.y);
            FMA2(acc[3][2], a1.y, c1.x); FMA2(acc[3][3], a1.y, c1.y);
        }
        __syncthreads();
        buf ^= 1;
    }

    float4 bv = *(const float4*)(bb + nq + 4 * tn);
    #pragma unroll
    for (int i = 0; i < 4; i++) {
        F2 u0, u1, u2, u3;
        u0.u = acc[i][0]; u1.u = acc[i][1]; u2.u = acc[i][2]; u3.u = acc[i][3];
        const int mA = m0 + (4 * tm + i) * 2;
        float4 r0 = make_float4(u0.f.x + bv.x, u1.f.x + bv.y, u2.f.x + bv.z, u3.f.x + bv.w);
        float4 r1 = make_float4(u0.f.y + bv.x, u1.f.y + bv.y, u2.f.y + bv.z, u3.f.y + bv.w);
        *(float4*)(g_xp + (size_t)mA * G4 + n0 + 4 * tn)       = r0;
        *(float4*)(g_xp + (size_t)(mA + 1) * G4 + n0 + 4 * tn) = r1;
    }
}

// ===========================================================================
// Phase 2: persistent scan. 128 CTAs x 512 thr.
// CTA owns 32 gate-rows (8 hidden x 4 gates); Wh slice SMEM-resident as
// k-pair f32x2 for all 512 steps.
// Warp w: rg = w&3 (8 rows, warp-uniform -> w-loads 8-way broadcast),
//         bset = w>>2. Lane: sl = lane&3 (k-slice of 4), bq = lane>>2.
// Thread tile: 2 batches (B0,B0+1) x 8 rows = 16 f2 acc (32 regs),
// inner loop software-pipelined (load i+1 while FMA i).
// ===========================================================================
#define WSR 34
#define HDR 66
#define SM_WS (512 * WSR * 8)       // 139264
#define SM_HD (2 * 64 * HDR * 8)    // 67584
#define SM_GB (64 * 33 * 4)         // 8448
#define SM_SCAN (SM_WS + SM_HD + SM_GB)

__device__ __forceinline__ float sigf(float x) { return 1.0f / (1.0f + __expf(-x)); }

__global__ __launch_bounds__(512, 1) void lstm_scan(
    const float* __restrict__ h0, const float* __restrict__ c0,
    const float* __restrict__ Whi, const float* __restrict__ Whf,
    const float* __restrict__ Whg, const float* __restrict__ Who,
    float* __restrict__ out)
{
    extern __shared__ char sm[];
    ull*   ws = (ull*)sm;                      // [512 kp][WSR]: (w[r][2kp],w[r][2kp+1]) at [kp*WSR+r]
    ull*   hd = (ull*)(sm + SM_WS);            // [2][64 b][HDR]: (h[b][2kp],h[b][2kp+1])
    float* gb = (float*)(sm + SM_WS + SM_HD);  // [64][33] gate preacts

    const int tid  = threadIdx.x;
    const int j0   = blockIdx.x * 8;
    const int w    = tid >> 5;
    const int lane = tid & 31;
    const int sl   = lane & 3;       // k-slice (4)
    const int bq   = lane >> 2;      // 0..7
    const int rg   = w & 3;          // warp-uniform gate/row-group
    const int bset = w >> 2;         // 0..3
    const int B0   = bset * 16 + bq * 2;

    // one-time: pack this CTA's 32 Wh rows into SMEM (row r = gate*8 + jl)
    const float* Wm[4] = {Whi, Whf, Whg, Who};
    for (int r = 0; r < 32; r++) {
        const float* src = Wm[r >> 3] + (size_t)(j0 + (r & 7)) * Hh;
        for (int kp = tid; kp < 512; kp += 512) {
            F2 tt; tt.f = *(const float2*)(src + 2 * kp);
            ws[kp * WSR + r] = tt.u;
        }
    }

    const int rb = tid >> 3, rj = tid & 7;     // gate-phase: 1 cell per thread
    float creg = c0[rb * Hh + j0 + rj];
    __syncthreads();

    for (int t = 0; t < Tt; t++) {
        const float* hcur = (t == 0) ? h0 : g_h[t & 1];
        float* hnxt = g_h[(t + 1) & 1];

        // prefetch x_proj contributions (hidden under mainloop)
        float xq0, xq1, xq2, xq3;
        {
            const float* xb = g_xp + ((size_t)rb * Tt + t) * G4 + j0 + rj;
            xq0 = xb[0]; xq1 = xb[Hh]; xq2 = xb[2 * Hh]; xq3 = xb[3 * Hh];
        }

        ull acc[2][8];
        #pragma unroll
        for (int j = 0; j < 2; j++)
            #pragma unroll
            for (int r = 0; r < 8; r++) acc[j][r] = 0ull;

        // stage chunk 0 (k 0..127): 512 thr x 4 float4, conflict-free STS.128
        #pragma unroll
        for (int it = 0; it < 4; it++) {
            int idx = it * 512 + tid;
            int b = idx >> 5, k4 = idx & 31;
            float4 v = *(const float4*)(hcur + b * Hh + k4 * 4);
            F2 t0, t1; t0.f = make_float2(v.x, v.y); t1.f = make_float2(v.z, v.w);
            ulonglong2 w2; w2.x = t0.u; w2.y = t1.u;
            *(ulonglong2*)(hd + b * HDR + k4 * 2) = w2;
        }
        __syncthreads();

        int buf = 0;
        for (int ch = 0; ch < 8; ch++) {
            float4 pre0, pre1, pre2, pre3;
            const bool has = (ch < 7);
            if (has) {                  // LDG next chunk first (hide L2 latency)
                const float* hsrc = hcur + (ch + 1) * 128;
                int i0 = tid;             pre0 = *(const float4*)(hsrc + (i0 >> 5) * Hh + (i0 & 31) * 4);
                int i1 = 512 + tid;       pre1 = *(const float4*)(hsrc + (i1 >> 5) * Hh + (i1 & 31) * 4);
                int i2 = 1024 + tid;      pre2 = *(const float4*)(hsrc + (i2 >> 5) * Hh + (i2 & 31) * 4);
                int i3 = 1536 + tid;      pre3 = *(const float4*)(hsrc + (i3 >> 5) * Hh + (i3 & 31) * 4);
            }
            const ull* hb = hd + (size_t)buf * 64 * HDR;
            const ull* wchunk = ws + (size_t)(ch * 64) * WSR + rg * 8;

            // ---- pipelined mainloop: 16 iters, kl = i*4 + sl ----
            const ull* wp = wchunk + (size_t)sl * WSR;
            ulonglong2 wA = *(const ulonglong2*)(wp);
            ulonglong2 wB = *(const ulonglong2*)(wp + 2);
            ulonglong2 wC = *(const ulonglong2*)(wp + 4);
            ulonglong2 wD = *(const ulonglong2*)(wp + 6);
            ull hv0 = hb[(B0 + 0) * HDR + sl];
            ull hv1 = hb[(B0 + 1) * HDR + sl];
            #pragma unroll
            for (int i = 0; i < 16; i++) {
                ulonglong2 nA, nB, nC, nD; ull nh0, nh1;
                if (i < 15) {
                    const int kn = (i + 1) * 4 + sl;
                    const ull* np = wchunk + (size_t)kn * WSR;
                    nA = *(const ulonglong2*)(np);
                    nB = *(const ulonglong2*)(np + 2);
                    nC = *(const ulonglong2*)(np + 4);
                    nD = *(const ulonglong2*)(np + 6);
                    nh0 = hb[(B0 + 0) * HDR + kn];
                    nh1 = hb[(B0 + 1) * HDR + kn];
                }
                FMA2(acc[0][0], hv0, wA.x); FMA2(acc[0][1], hv0, wA.y);
                FMA2(acc[0][2], hv0, wB.x); FMA2(acc[0][3], hv0, wB.y);
                FMA2(acc[0][4], hv0, wC.x); FMA2(acc[0][5], hv0, wC.y);
                FMA2(acc[0][6], hv0, wD.x); FMA2(acc[0][7], hv0, wD.y);
                FMA2(acc[1][0], hv1, wA.x); FMA2(acc[1][1], hv1, wA.y);
                FMA2(acc[1][2], hv1, wB.x); FMA2(acc[1][3], hv1, wB.y);
                FMA2(acc[1][4], hv1, wC.x); FMA2(acc[1][5], hv1, wC.y);
                FMA2(acc[1][6], hv1, wD.x); FMA2(acc[1][7], hv1, wD.y);
                if (i < 15) {
                    wA = nA; wB = nB; wC = nC; wD = nD;
                    hv0 = nh0; hv1 = nh1;
                }
            }

            if (has) {                  // STS next chunk after compute
                const int nb = buf ^ 1;
                ull* hdn = hd + (size_t)nb * 64 * HDR;
                F2 t0, t1; ulonglong2 w2;
                int i0 = tid;
                t0.f = make_float2(pre0.x, pre0.y); t1.f = make_float2(pre0.z, pre0.w);
                w2.x = t0.u; w2.y = t1.u;
                *(ulonglong2*)(hdn + (i0 >> 5) * HDR + (i0 & 31) * 2) = w2;
                int i1 = 512 + tid;
                t0.f = make_float2(pre1.x, pre1.y); t1.f = make_float2(pre1.z, pre1.w);
                w2.x = t0.u; w2.y = t1.u;
                *(ulonglong2*)(hdn + (i1 >> 5) * HDR + (i1 & 31) * 2) = w2;
                int i2 = 1024 + tid;
                t0.f = make_float2(pre2.x, pre2.y); t1.f = make_float2(pre2.z, pre2.w);
                w2.x = t0.u; w2.y = t1.u;
                *(ulonglong2*)(hdn + (i2 >> 5) * HDR + (i2 & 31) * 2) = w2;
                int i3 = 1536 + tid;
                t0.f = make_float2(pre3.x, pre3.y); t1.f = make_float2(pre3.z, pre3.w);
                w2.x = t0.u; w2.y = t1.u;
                *(ulonglong2*)(hdn + (i3 >> 5) * HDR + (i3 & 31) * 2) = w2;
            }
            __syncthreads();
            buf ^= 1;
        }

        // reduce 4 k-slices (xor over lane bits 0..1) + pair halves; sl==0 publishes
        #pragma unroll
        for (int j = 0; j < 2; j++)
            #pragma unroll
            for (int r = 0; r < 8; r++) {
                F2 u; u.u = acc[j][r];
                float v = u.f.x + u.f.y;
                v += __shfl_xor_sync(0xffffffffu, v, 1);
                v += __shfl_xor_sync(0xffffffffu, v, 2);
                if (sl == 0) gb[(B0 + j) * 33 + rg * 8 + r] = v;
            }
        __syncthreads();

        // gates + state update: one (b, j) cell per thread
        {
            const float* gr = gb + rb * 33;
            float gi = gr[rj]      + xq0;
            float gf = gr[8 + rj]  + xq1;
            float gg = gr[16 + rj] + xq2;
            float go = gr[24 + rj] + xq3;
            float iv = sigf(gi), fv = sigf(gf), ov = sigf(go);
            float gv = 2.0f * sigf(2.0f * gg) - 1.0f;
            creg = fv * creg + iv * gv;
            float hv = ov * (2.0f * sigf(2.0f * creg) - 1.0f);
            hnxt[rb * Hh + j0 + rj] = hv;
            out[((size_t)rb * Tt + t) * Hh + j0 + rj] = hv;
            if (t == Tt - 1) {
                out[HSEQ_N + rb * Hh + j0 + rj] = hv;
                out[HSEQ_N + Bb * Hh + rb * Hh + j0 + rj] = creg;
            }
        }

        if (t < Tt - 1) {                       // grid barrier
            __syncthreads();
            if (tid == 0) {
                __threadfence();                 // drain h stores (gpu scope)
                unsigned g = *(volatile unsigned*)&g_bar_gen;
                if (atomicAdd(&g_bar_count, 1u) == gridDim.x - 1u) {
                    atomicExch(&g_bar_count, 0u);
                    __threadfence();
                    atomicAdd(&g_bar_gen, 1u);
                } else {
                    while (*(volatile unsigned*)&g_bar_gen == g) __nanosleep(64);
                }
                __threadfence();                 // acquire before reading new h
            }
            __syncthreads();
        }
    }
}

// ===========================================================================
extern "C" void kernel_launch(void* const* d_in, const int* in_sizes, int n_in,
                              void* d_out, int out_size)
{
    (void)in_sizes; (void)n_in; (void)out_size;
    const float* x   = (const float*)d_in[0];
    const float* h0  = (const float*)d_in[1];
    const float* c0  = (const float*)d_in[2];
    const float* Wii = (const float*)d_in[3];
    const float* Whi = (const float*)d_in[4];
    const float* bi  = (const float*)d_in[5];
    const float* Wif = (const float*)d_in[6];
    const float* Whf = (const float*)d_in[7];
    const float* bf  = (const float*)d_in[8];
    const float* Wig = (const float*)d_in[9];
    const float* Whg = (const float*)d_in[10];
    const float* bg_ = (const float*)d_in[11];
    const float* Wio = (const float*)d_in[12];
    const float* Who = (const float*)d_in[13];
    const float* bo  = (const float*)d_in[14];
    float* out = (float*)d_out;

    xproj_kernel<<<16384, 256>>>(x, Wii, Wif, Wig, Wio, bi, bf, bg_, bo);

    static int attr_done = 0;
    if (!attr_done) {
        cudaFuncSetAttribute(lstm_scan,
                             cudaFuncAttributeMaxDynamicSharedMemorySize, SM_SCAN);
        attr_done = 1;
    }
    lstm_scan<<<128, 512, SM_SCAN>>>(h0, c0, Whi, Whf, Whg, Who, out);
}

// round 9
// speedup vs baseline: 1.5252x; 1.0901x over previous
#include <cuda_runtime.h>
#include <cuda_bf16.h>

typedef unsigned long long ull;
union F2 { float2 f; ull u; };
#define FMA2(c,a,b) asm("fma.rn.f32x2 %0, %1, %2, %0;" : "+l"(c) : "l"(a), "l"(b))

#define Bb 64
#define Tt 512
#define Hh 1024
#define G4 4096
#define HSEQ_N (Bb*Tt*Hh)

// scratch (device globals: allocation-free rule)
__device__ float g_xp[(size_t)Bb * Tt * G4];   // 512 MB x_proj
__device__ float g_h[2][Bb * Hh];              // double-buffered h
__device__ unsigned g_bar_count;
__device__ unsigned g_bar_gen;

// ===========================================================================
// Phase 1: g_xp[M=32768, 4096] = input[M,1024] @ Wi^T + b
// Tile 128x64x16, 256 threads, 32 outputs/thread, packed f32x2 FMA.
// Stage-before-compute (transients dead before compute) + 2 CTAs/SM.
// (unchanged from R8 — measured near fp32 ceiling)
// ===========================================================================
#define PM 128
#define PN 64
#define PK 16

__global__ __launch_bounds__(256, 2) void xproj_kernel(
    const float* __restrict__ A,
    const float* __restrict__ W0, const float* __restrict__ W1,
    const float* __restrict__ W2, const float* __restrict__ W3,
    const float* __restrict__ b0, const float* __restrict__ b1,
    const float* __restrict__ b2, const float* __restrict__ b3)
{
    __shared__ __align__(16) ull as_[2][PK][PM / 2];  // (A[2m],A[2m+1]) row pairs
    __shared__ __align__(16) ull bs_[2][PK][PN];      // (w,w) duplicated

    const int tid = threadIdx.x;
    const int nTile = blockIdx.x & 63;
    const int mTile = blockIdx.x >> 6;
    const int m0 = mTile * PM;
    const int n0 = nTile * PN;
    const int q = n0 >> 10;
    const float* W  = (q == 0) ? W0 : (q == 1) ? W1 : (q == 2) ? W2 : W3;
    const float* bb = (q == 0) ? b0 : (q == 1) ? b1 : (q == 2) ? b2 : b3;
    const int nq = n0 & 1023;

    const int ar = tid >> 1, ak = (tid & 1) * 8;
    const int wr = tid >> 2, wk = (tid & 3) * 4;
    const int tn = tid & 15, tm = tid >> 4;

    ull acc[4][4];
    #pragma unroll
    for (int i = 0; i < 4; i++)
        #pragma unroll
        for (int j = 0; j < 4; j++) acc[i][j] = 0ull;

    const float* Arow = A + (size_t)(m0 + ar) * 1024;
    const float* Wrow = W + (size_t)(nq + wr) * 1024;
    const int mp = ar >> 1, hl = ar & 1;

    {   // stage chunk 0
        float4 v0 = *(const float4*)(Arow + ak);
        float4 v1 = *(const float4*)(Arow + ak + 4);
        float4 w  = *(const float4*)(Wrow + wk);
        #pragma unroll
        for (int i = 0; i < 4; i++) {
            ((float*)&as_[0][ak + i][mp])[hl]     = (&v0.x)[i];
            ((float*)&as_[0][ak + 4 + i][mp])[hl] = (&v1.x)[i];
            F2 t; t.f = make_float2((&w.x)[i], (&w.x)[i]);
            bs_[0][wk + i][wr] = t.u;
        }
    }
    __syncthreads();

    int buf = 0;
    for (int ch = 0; ch < 64; ch++) {
        if (ch < 63) {                      // stage next chunk, then compute
            const int k0 = (ch + 1) * PK;
            const int nb = buf ^ 1;
            float4 v0 = *(const float4*)(Arow + k0 + ak);
            float4 v1 = *(const float4*)(Arow + k0 + ak + 4);
            float4 w  = *(const float4*)(Wrow + k0 + wk);
            #pragma unroll
            for (int i = 0; i < 4; i++) {
                ((float*)&as_[nb][ak + i][mp])[hl]     = (&v0.x)[i];
                ((float*)&as_[nb][ak + 4 + i][mp])[hl] = (&v1.x)[i];
                F2 t; t.f = make_float2((&w.x)[i], (&w.x)[i]);
                bs_[nb][wk + i][wr] = t.u;
            }
        }
        #pragma unroll
        for (int kk = 0; kk < PK; kk++) {
            ulonglong2 a0 = *(const ulonglong2*)&as_[buf][kk][4 * tm];
            ulonglong2 a1 = *(const ulonglong2*)&as_[buf][kk][4 * tm + 2];
            ulonglong2 c0 = *(const ulonglong2*)&bs_[buf][kk][4 * tn];
            ulonglong2 c1 = *(const ulonglong2*)&bs_[buf][kk][4 * tn + 2];
            FMA2(acc[0][0], a0.x, c0.x); FMA2(acc[0][1], a0.x, c0.y);
            FMA2(acc[0][2], a0.x, c1.x); FMA2(acc[0][3], a0.x, c1.y);
            FMA2(acc[1][0], a0.y, c0.x); FMA2(acc[1][1], a0.y, c0.y);
            FMA2(acc[1][2], a0.y, c1.x); FMA2(acc[1][3], a0.y, c1.y);
            FMA2(acc[2][0], a1.x, c0.x); FMA2(acc[2][1], a1.x, c0.y);
            FMA2(acc[2][2], a1.x, c1.x); FMA2(acc[2][3], a1.x, c1.y);
            FMA2(acc[3][0], a1.y, c0.x); FMA2(acc[3][1], a1.y, c0.y);
            FMA2(acc[3][2], a1.y, c1.x); FMA2(acc[3][3], a1.y, c1.y);
        }
        __syncthreads();
        buf ^= 1;
    }

    float4 bv = *(const float4*)(bb + nq + 4 * tn);
    #pragma unroll
    for (int i = 0; i < 4; i++) {
        F2 u0, u1, u2, u3;
        u0.u = acc[i][0]; u1.u = acc[i][1]; u2.u = acc[i][2]; u3.u = acc[i][3];
        const int mA = m0 + (4 * tm + i) * 2;
        float4 r0 = make_float4(u0.f.x + bv.x, u1.f.x + bv.y, u2.f.x + bv.z, u3.f.x + bv.w);
        float4 r1 = make_float4(u0.f.y + bv.x, u1.f.y + bv.y, u2.f.y + bv.z, u3.f.y + bv.w);
        *(float4*)(g_xp + (size_t)mA * G4 + n0 + 4 * tn)       = r0;
        *(float4*)(g_xp + (size_t)(mA + 1) * G4 + n0 + 4 * tn) = r1;
    }
}

// ===========================================================================
// Phase 2: persistent scan. 128 CTAs x 512 thr (16 warps, 4/SMSP).
// CTA owns 32 gate-rows (8 hidden x 4 gates); Wh slice SMEM-resident as
// k-pair f32x2 for all 512 steps.
// Warp w: rg = w&3 (8 rows, warp-uniform -> w-loads broadcast), bset = w>>2.
// Lane: sl = lane&7 (k-slice of 8), bq = lane>>3 -> B0 = bset*16 + bq*4.
// Thread tile: 4 batches x 8 rows = 32 f2 acc (64 regs). NO pipelining,
// NO LDG-hold: 4 warps/SMSP cover LDS latency; regs ~110 (no spill).
// ===========================================================================
#define WSR 34
#define HDR 66
#define SM_WS (512 * WSR * 8)       // 139264
#define SM_HD (2 * 64 * HDR * 8)    // 67584
#define SM_GB (64 * 33 * 4)         // 8448
#define SM_SCAN (SM_WS + SM_HD + SM_GB)

__device__ __forceinline__ float sigf(float x) { return 1.0f / (1.0f + __expf(-x)); }

__global__ __launch_bounds__(512, 1) void lstm_scan(
    const float* __restrict__ h0, const float* __restrict__ c0,
    const float* __restrict__ Whi, const float* __restrict__ Whf,
    const float* __restrict__ Whg, const float* __restrict__ Who,
    float* __restrict__ out)
{
    extern __shared__ char sm[];
    ull*   ws = (ull*)sm;                      // [512 kp][WSR]: (w[r][2kp],w[r][2kp+1]) at [kp*WSR+r]
    ull*   hd = (ull*)(sm + SM_WS);            // [2][64 b][HDR]: (h[b][2kp],h[b][2kp+1])
    float* gb = (float*)(sm + SM_WS + SM_HD);  // [64][33] gate preacts

    const int tid  = threadIdx.x;
    const int j0   = blockIdx.x * 8;
    const int w    = tid >> 5;
    const int lane = tid & 31;
    const int sl   = lane & 7;       // k-slice (8)
    const int bq   = lane >> 3;      // 0..3
    const int rg   = w & 3;          // warp-uniform gate/row-group
    const int bset = w >> 2;         // 0..3
    const int B0   = bset * 16 + bq * 4;

    // one-time: pack this CTA's 32 Wh rows into SMEM (row r = gate*8 + jl)
    const float* Wm[4] = {Whi, Whf, Whg, Who};
    for (int r = 0; r < 32; r++) {
        const float* src = Wm[r >> 3] + (size_t)(j0 + (r & 7)) * Hh;
        for (int kp = tid; kp < 512; kp += 512) {
            F2 tt; tt.f = *(const float2*)(src + 2 * kp);
            ws[kp * WSR + r] = tt.u;
        }
    }

    const int rb = tid >> 3, rj = tid & 7;     // gate-phase: 1 cell per thread
    float creg = c0[rb * Hh + j0 + rj];
    __syncthreads();

    for (int t = 0; t < Tt; t++) {
        const float* hcur = (t == 0) ? h0 : g_h[t & 1];
        float* hnxt = g_h[(t + 1) & 1];

        // prefetch x_proj contributions (hidden under mainloop)
        float xq0, xq1, xq2, xq3;
        {
            const float* xb = g_xp + ((size_t)rb * Tt + t) * G4 + j0 + rj;
            xq0 = xb[0]; xq1 = xb[Hh]; xq2 = xb[2 * Hh]; xq3 = xb[3 * Hh];
        }

        ull acc[4][8];
        #pragma unroll
        for (int j = 0; j < 4; j++)
            #pragma unroll
            for (int r = 0; r < 8; r++) acc[j][r] = 0ull;

        // stage chunk 0 (k 0..127): 512 thr x 4 float4, conflict-free STS.128
        #pragma unroll
        for (int it = 0; it < 4; it++) {
            int idx = it * 512 + tid;
            int b = idx >> 5, k4 = idx & 31;
            float4 v = *(const float4*)(hcur + b * Hh + k4 * 4);
            F2 t0, t1; t0.f = make_float2(v.x, v.y); t1.f = make_float2(v.z, v.w);
            ulonglong2 w2; w2.x = t0.u; w2.y = t1.u;
            *(ulonglong2*)(hd + b * HDR + k4 * 2) = w2;
        }
        __syncthreads();

        int buf = 0;
        for (int ch = 0; ch < 8; ch++) {
            if (ch < 7) {          // stage next chunk (transients die here)
                const int nb = buf ^ 1;
                const float* hsrc = hcur + (ch + 1) * 128;
                ull* hdn = hd + (size_t)nb * 64 * HDR;
                #pragma unroll
                for (int it = 0; it < 4; it++) {
                    int idx = it * 512 + tid;
                    int b = idx >> 5, k4 = idx & 31;
                    float4 v = *(const float4*)(hsrc + b * Hh + k4 * 4);
                    F2 t0, t1; t0.f = make_float2(v.x, v.y); t1.f = make_float2(v.z, v.w);
                    ulonglong2 w2; w2.x = t0.u; w2.y = t1.u;
                    *(ulonglong2*)(hdn + b * HDR + k4 * 2) = w2;
                }
            }
            const ull* hb = hd + (size_t)buf * 64 * HDR;
            const ull* wchunk = ws + (size_t)(ch * 64) * WSR + rg * 8;
            #pragma unroll
            for (int i = 0; i < 8; i++) {
                const int kl = i * 8 + sl;
                const ull* wp = wchunk + (size_t)kl * WSR;
                ulonglong2 wA = *(const ulonglong2*)(wp);
                ulonglong2 wB = *(const ulonglong2*)(wp + 2);
                ulonglong2 wC = *(const ulonglong2*)(wp + 4);
                ulonglong2 wD = *(const ulonglong2*)(wp + 6);
                ull hv0 = hb[(B0 + 0) * HDR + kl];
                ull hv1 = hb[(B0 + 1) * HDR + kl];
                ull hv2 = hb[(B0 + 2) * HDR + kl];
                ull hv3 = hb[(B0 + 3) * HDR + kl];
                FMA2(acc[0][0], hv0, wA.x); FMA2(acc[0][1], hv0, wA.y);
                FMA2(acc[0][2], hv0, wB.x); FMA2(acc[0][3], hv0, wB.y);
                FMA2(acc[0][4], hv0, wC.x); FMA2(acc[0][5], hv0, wC.y);
                FMA2(acc[0][6], hv0, wD.x); FMA2(acc[0][7], hv0, wD.y);
                FMA2(acc[1][0], hv1, wA.x); FMA2(acc[1][1], hv1, wA.y);
                FMA2(acc[1][2], hv1, wB.x); FMA2(acc[1][3], hv1, wB.y);
                FMA2(acc[1][4], hv1, wC.x); FMA2(acc[1][5], hv1, wC.y);
                FMA2(acc[1][6], hv1, wD.x); FMA2(acc[1][7], hv1, wD.y);
                FMA2(acc[2][0], hv2, wA.x); FMA2(acc[2][1], hv2, wA.y);
                FMA2(acc[2][2], hv2, wB.x); FMA2(acc[2][3], hv2, wB.y);
                FMA2(acc[2][4], hv2, wC.x); FMA2(acc[2][5], hv2, wC.y);
                FMA2(acc[2][6], hv2, wD.x); FMA2(acc[2][7], hv2, wD.y);
                FMA2(acc[3][0], hv3, wA.x); FMA2(acc[3][1], hv3, wA.y);
                FMA2(acc[3][2], hv3, wB.x); FMA2(acc[3][3], hv3, wB.y);
                FMA2(acc[3][4], hv3, wC.x); FMA2(acc[3][5], hv3, wC.y);
                FMA2(acc[3][6], hv3, wD.x); FMA2(acc[3][7], hv3, wD.y);
            }
            __syncthreads();
            buf ^= 1;
        }

        // reduce 8 k-slices (xor over lane bits 0..2) + pair halves; sl==0 publishes
        #pragma unroll
        for (int j = 0; j < 4; j++)
            #pragma unroll
            for (int r = 0; r < 8; r++) {
                F2 u; u.u = acc[j][r];
                float v = u.f.x + u.f.y;
                v += __shfl_xor_sync(0xffffffffu, v, 1);
                v += __shfl_xor_sync(0xffffffffu, v, 2);
                v += __shfl_xor_sync(0xffffffffu, v, 4);
                if (sl == 0) gb[(B0 + j) * 33 + rg * 8 + r] = v;
            }
        __syncthreads();

        // gates + state update: one (b, j) cell per thread
        {
            const float* gr = gb + rb * 33;
            float gi = gr[rj]      + xq0;
            float gf = gr[8 + rj]  + xq1;
            float gg = gr[16 + rj] + xq2;
            float go = gr[24 + rj] + xq3;
            float iv = sigf(gi), fv = sigf(gf), ov = sigf(go);
            float gv = 2.0f * sigf(2.0f * gg) - 1.0f;
            creg = fv * creg + iv * gv;
            float hv = ov * (2.0f * sigf(2.0f * creg) - 1.0f);
            hnxt[rb * Hh + j0 + rj] = hv;
            out[((size_t)rb * Tt + t) * Hh + j0 + rj] = hv;
            if (t == Tt - 1) {
                out[HSEQ_N + rb * Hh + j0 + rj] = hv;
                out[HSEQ_N + Bb * Hh + rb * Hh + j0 + rj] = creg;
            }
        }

        if (t < Tt - 1) {                       // grid barrier
            __syncthreads();
            if (tid == 0) {
                __threadfence();                 // drain h stores (gpu scope)
                unsigned g = *(volatile unsigned*)&g_bar_gen;
                if (atomicAdd(&g_bar_count, 1u) == gridDim.x - 1u) {
                    atomicExch(&g_bar_count, 0u);
                    __threadfence();
                    atomicAdd(&g_bar_gen, 1u);
                } else {
                    while (*(volatile unsigned*)&g_bar_gen == g) __nanosleep(64);
                }
                __threadfence();                 // acquire before reading new h
            }
            __syncthreads();
        }
    }
}

// ===========================================================================
extern "C" void kernel_launch(void* const* d_in, const int* in_sizes, int n_in,
                              void* d_out, int out_size)
{
    (void)in_sizes; (void)n_in; (void)out_size;
    const float* x   = (const float*)d_in[0];
    const float* h0  = (const float*)d_in[1];
    const float* c0  = (const float*)d_in[2];
    const float* Wii = (const float*)d_in[3];
    const float* Whi = (const float*)d_in[4];
    const float* bi  = (const float*)d_in[5];
    const float* Wif = (const float*)d_in[6];
    const float* Whf = (const float*)d_in[7];
    const float* bf  = (const float*)d_in[8];
    const float* Wig = (const float*)d_in[9];
    const float* Whg = (const float*)d_in[10];
    const float* bg_ = (const float*)d_in[11];
    const float* Wio = (const float*)d_in[12];
    const float* Who = (const float*)d_in[13];
    const float* bo  = (const float*)d_in[14];
    float* out = (float*)d_out;

    xproj_kernel<<<16384, 256>>>(x, Wii, Wif, Wig, Wio, bi, bf, bg_, bo);

    static int attr_done = 0;
    if (!attr_done) {
        cudaFuncSetAttribute(lstm_scan,
                             cudaFuncAttributeMaxDynamicSharedMemorySize, SM_SCAN);
        attr_done = 1;
    }
    lstm_scan<<<128, 512, SM_SCAN>>>(h0, c0, Whi, Whf, Whg, Who, out);
}

// round 11
// speedup vs baseline: 2.2928x; 1.5033x over previous
#include <cuda_runtime.h>
#include <cuda_bf16.h>
#include <cstdint>

typedef unsigned long long ull;
union F2 { float2 f; ull u; };
#define FMA2(c,a,b) asm("fma.rn.f32x2 %0, %1, %2, %0;" : "+l"(c) : "l"(a), "l"(b))

#define Bb 64
#define Tt 512
#define Hh 1024
#define G4 4096
#define KE 3072
#define HSEQ_N (Bb*Tt*Hh)

// scratch (device globals: allocation-free rule)
__device__ float g_xp[(size_t)Bb * Tt * G4];          // 512 MB x_proj
__device__ __nv_bfloat16 g_abf[(size_t)Bb * Tt * KE]; // 192 MB  A' = [hi, lo, hi]
__device__ __nv_bfloat16 g_wbf[(size_t)G4 * KE];      // 24 MB   W' = [hi, hi, lo]
__device__ float g_h[2][Bb * Hh];
__device__ unsigned g_bar_count;
__device__ unsigned g_bar_gen;

__device__ __forceinline__ uint32_t smem_u32(const void* p) {
    uint32_t a;
    asm("{ .reg .u64 t; cvta.to.shared.u64 t, %1; cvt.u32.u64 %0, t; }" : "=r"(a) : "l"(p));
    return a;
}

#define LDMX4(r0,r1,r2,r3,addr) \
    asm volatile("ldmatrix.sync.aligned.m8n8.x4.shared.b16 {%0,%1,%2,%3}, [%4];" \
        : "=r"(r0), "=r"(r1), "=r"(r2), "=r"(r3) : "r"(addr))

#define MMA16816(d,a0,a1,a2,a3,b0,b1) \
    asm volatile("mma.sync.aligned.m16n8k16.row.col.f32.bf16.bf16.f32 " \
        "{%0,%1,%2,%3}, {%4,%5,%6,%7}, {%8,%9}, {%0,%1,%2,%3};" \
        : "+f"((d)[0]), "+f"((d)[1]), "+f"((d)[2]), "+f"((d)[3]) \
        : "r"(a0), "r"(a1), "r"(a2), "r"(a3), "r"(b0), "r"(b1))

// ---------------------------------------------------------------------------
// bf16-split conversions: x = hi + lo
// A' cols: [0,1024)=hi [1024,2048)=lo [2048,3072)=hi
// W' cols: [0,1024)=hi [1024,2048)=hi [2048,3072)=lo
// ---------------------------------------------------------------------------
__global__ __launch_bounds__(256) void conv_a_kernel(const float* __restrict__ x)
{
    size_t base = ((size_t)blockIdx.x * 256 + threadIdx.x) * 2;
    int m = (int)(base >> 10), k = (int)(base & 1023);
    float2 a = *(const float2*)(x + base);
    __nv_bfloat16 h0 = __float2bfloat16(a.x);
    __nv_bfloat16 h1 = __float2bfloat16(a.y);
    __nv_bfloat16 l0 = __float2bfloat16(a.x - __bfloat162float(h0));
    __nv_bfloat16 l1 = __float2bfloat16(a.y - __bfloat162float(h1));
    __nv_bfloat162 hh; hh.x = h0; hh.y = h1;
    __nv_bfloat162 ll; ll.x = l0; ll.y = l1;
    __nv_bfloat16* dst = g_abf + (size_t)m * KE + k;
    *(__nv_bfloat162*)(dst)        = hh;
    *(__nv_bfloat162*)(dst + 1024) = ll;
    *(__nv_bfloat162*)(dst + 2048) = hh;
}

__global__ __launch_bounds__(256) void conv_w_kernel(
    const float* __restrict__ W0, const float* __restrict__ W1,
    const float* __restrict__ W2, const float* __restrict__ W3)
{
    size_t base = ((size_t)blockIdx.x * 256 + threadIdx.x) * 2;
    int n = (int)(base >> 10), k = (int)(base & 1023);
    int q = n >> 10;
    const float* W = (q == 0) ? W0 : (q == 1) ? W1 : (q == 2) ? W2 : W3;
    float2 a = *(const float2*)(W + (size_t)(n & 1023) * 1024 + k);
    __nv_bfloat16 h0 = __float2bfloat16(a.x);
    __nv_bfloat16 h1 = __float2bfloat16(a.y);
    __nv_bfloat16 l0 = __float2bfloat16(a.x - __bfloat162float(h0));
    __nv_bfloat16 l1 = __float2bfloat16(a.y - __bfloat162float(h1));
    __nv_bfloat162 hh; hh.x = h0; hh.y = h1;
    __nv_bfloat162 ll; ll.x = l0; ll.y = l1;
    __nv_bfloat16* dst = g_wbf + (size_t)n * KE + k;
    *(__nv_bfloat162*)(dst)        = hh;
    *(__nv_bfloat162*)(dst + 1024) = hh;
    *(__nv_bfloat162*)(dst + 2048) = ll;
}

// ---------------------------------------------------------------------------
// mma.sync bf16 GEMM: g_xp[32768,4096] = A'[32768,3072] @ W'[4096,3072]^T + b
// CTA 128x128, 8 warps (4m x 2n), warp tile 32x64, K-chunk 32, double buffer.
// smem layout (per 128x32 bf16 tile): 64 lines of 128B; line L holds rows
// 2L,2L+1; 16B chunk (row r, seg s in 0..3) at position p'=((r&1)*4+s)^(L&7).
// Conflict-free for staging STS.128 and all ldmatrix phases (verified).
// ---------------------------------------------------------------------------
__global__ __launch_bounds__(256) void gemm_mma(
    const float* __restrict__ b0, const float* __restrict__ b1,
    const float* __restrict__ b2, const float* __restrict__ b3)
{
    __shared__ __align__(128) char smA[2][8192];
    __shared__ __align__(128) char smB[2][8192];

    const int tid = threadIdx.x, wid = tid >> 5, lane = tid & 31;
    const int mTile = blockIdx.x >> 5, nTile = blockIdx.x & 31;
    const int m0 = mTile * 128, n0 = nTile * 128;
    const int m_w = (wid & 3) * 32;      // warp m base (32 rows)
    const int n_wb = (wid >> 2) * 64;    // warp n base (64 cols)

    const uint32_t sA = smem_u32(smA);
    const uint32_t sB = smem_u32(smB);

    // staging mapping: idx 0..511 -> row=idx>>2, seg=idx&3
    const int r0i = tid >> 2, s0 = tid & 3;
    const int r1i = (tid + 256) >> 2, s1 = (tid + 256) & 3;
    const uint32_t st0 = (uint32_t)((r0i >> 1) * 128 + ((((r0i & 1) * 4 + s0) ^ ((r0i >> 1) & 7)) * 16));
    const uint32_t st1 = (uint32_t)((r1i >> 1) * 128 + ((((r1i & 1) * 4 + s1) ^ ((r1i >> 1) & 7)) * 16));
    const __nv_bfloat16* gA0 = g_abf + (size_t)(m0 + r0i) * KE + s0 * 8;
    const __nv_bfloat16* gA1 = g_abf + (size_t)(m0 + r1i) * KE + s1 * 8;
    const __nv_bfloat16* gB0 = g_wbf + (size_t)(n0 + r0i) * KE + s0 * 8;
    const __nv_bfloat16* gB1 = g_wbf + (size_t)(n0 + r1i) * KE + s1 * 8;

    // ldmatrix per-lane offsets (ks=0; ks=1 = XOR 32)
    const int row_l = lane & 15, sh = lane >> 4;
    uint32_t offA[2], offB[4];
    #pragma unroll
    for (int a = 0; a < 2; a++) {
        int r = m_w + a * 16 + row_l;
        int L = r >> 1, p = (r & 1) * 4 + sh;
        offA[a] = (uint32_t)(L * 128 + ((p ^ (L & 7)) * 16));
    }
    #pragma unroll
    for (int b = 0; b < 4; b++) {
        int r = n_wb + b * 16 + row_l;
        int L = r >> 1, p = (r & 1) * 4 + sh;
        offB[b] = (uint32_t)(L * 128 + ((p ^ (L & 7)) * 16));
    }

    float acc[2][8][4];
    #pragma unroll
    for (int a = 0; a < 2; a++)
        #pragma unroll
        for (int n = 0; n < 8; n++)
            #pragma unroll
            for (int c = 0; c < 4; c++) acc[a][n][c] = 0.0f;

    // stage chunk 0
    *(uint4*)(smA[0] + st0) = *(const uint4*)(gA0);
    *(uint4*)(smA[0] + st1) = *(const uint4*)(gA1);
    *(uint4*)(smB[0] + st0) = *(const uint4*)(gB0);
    *(uint4*)(smB[0] + st1) = *(const uint4*)(gB1);
    __syncthreads();

    int buf = 0;
    for (int ch = 0; ch < 96; ch++) {
        if (ch < 95) {                      // stage next chunk (transients die)
            const int nb = buf ^ 1;
            const int ko = (ch + 1) * 32;
            *(uint4*)(smA[nb] + st0) = *(const uint4*)(gA0 + ko);
            *(uint4*)(smA[nb] + st1) = *(const uint4*)(gA1 + ko);
            *(uint4*)(smB[nb] + st0) = *(const uint4*)(gB0 + ko);
            *(uint4*)(smB[nb] + st1) = *(const uint4*)(gB1 + ko);
        }
        const uint32_t bA = sA + buf * 8192;
        const uint32_t bB = sB + buf * 8192;
        #pragma unroll
        for (int ks = 0; ks < 2; ks++) {
            const uint32_t kx = ks * 32;
            uint32_t af[2][4], bf_[4][4];
            #pragma unroll
            for (int a = 0; a < 2; a++)
                LDMX4(af[a][0], af[a][1], af[a][2], af[a][3], (bA + offA[a]) ^ kx);
            #pragma unroll
            for (int b = 0; b < 4; b++)
                LDMX4(bf_[b][0], bf_[b][1], bf_[b][2], bf_[b][3], (bB + offB[b]) ^ kx);
            #pragma unroll
            for (int a = 0; a < 2; a++)
                #pragma unroll
                for (int nt = 0; nt < 8; nt++) {
                    const int bt = nt >> 1, hl = nt & 1;
                    MMA16816(acc[a][nt], af[a][0], af[a][1], af[a][2], af[a][3],
                             bf_[bt][hl], bf_[bt][hl + 2]);
                }
        }
        __syncthreads();
        buf ^= 1;
    }

    // epilogue: + bias -> g_xp
    const int q = n0 >> 10;
    const float* bp = (q == 0) ? b0 : (q == 1) ? b1 : (q == 2) ? b2 : b3;
    const int nqb = (n0 & 1023) + n_wb;
    #pragma unroll
    for (int a = 0; a < 2; a++) {
        const int row0 = m0 + m_w + a * 16 + (lane >> 2);
        #pragma unroll
        for (int nt = 0; nt < 8; nt++) {
            const int col = n_wb + nt * 8 + (lane & 3) * 2;
            const float bv0 = __ldg(bp + nqb + nt * 8 + (lane & 3) * 2);
            const float bv1 = __ldg(bp + nqb + nt * 8 + (lane & 3) * 2 + 1);
            float2 v0 = make_float2(acc[a][nt][0] + bv0, acc[a][nt][1] + bv1);
            float2 v1 = make_float2(acc[a][nt][2] + bv0, acc[a][nt][3] + bv1);
            *(float2*)(g_xp + (size_t)row0 * G4 + n0 + col)       = v0;
            *(float2*)(g_xp + (size_t)(row0 + 8) * G4 + n0 + col) = v1;
        }
    }
}

// ===========================================================================
// Phase 2: persistent scan — R5's exact proven kernel (256 thr, 8b x 8r tile)
// ===========================================================================
#define WSR 34
#define HDR 66
#define SM_WS (512 * WSR * 8)       // 139264
#define SM_HD (2 * 64 * HDR * 8)    // 67584
#define SM_GB (64 * 33 * 4)         // 8448
#define SM_SCAN (SM_WS + SM_HD + SM_GB)

__device__ __forceinline__ float sigf(float x) { return 1.0f / (1.0f + __expf(-x)); }

__global__ __launch_bounds__(256, 1) void lstm_scan(
    const float* __restrict__ h0, const float* __restrict__ c0,
    const float* __restrict__ Whi, const float* __restrict__ Whf,
    const float* __restrict__ Whg, const float* __restrict__ Who,
    float* __restrict__ out)
{
    extern __shared__ char sm[];
    ull*   ws = (ull*)sm;
    ull*   hd = (ull*)(sm + SM_WS);
    float* gb = (float*)(sm + SM_WS + SM_HD);

    const int tid = threadIdx.x;
    const int j0 = blockIdx.x * 8;
    const int sl = tid & 7;
    const int ow = tid >> 3;
    const int rg = ow & 3;
    const int bg = ow >> 2;

    const float* Wm[4] = {Whi, Whf, Whg, Who};
    for (int r = 0; r < 32; r++) {
        const float* src = Wm[r >> 3] + (size_t)(j0 + (r & 7)) * Hh;
        for (int kp = tid; kp < 512; kp += 256) {
            F2 tt; tt.f = *(const float2*)(src + 2 * kp);
            ws[kp * WSR + r] = tt.u;
        }
    }

    const int rb = tid >> 2, rj = tid & 3;
    float cr0 = c0[rb * Hh + j0 + rj];
    float cr1 = c0[rb * Hh + j0 + rj + 4];
    __syncthreads();

    for (int t = 0; t < Tt; t++) {
        const float* hcur = (t == 0) ? h0 : g_h[t & 1];
        float* hnxt = g_h[(t + 1) & 1];

        float xq[2][4];
        {
            const float* xb = g_xp + ((size_t)rb * Tt + t) * G4;
            #pragma unroll
            for (int p = 0; p < 2; p++)
                #pragma unroll
                for (int q = 0; q < 4; q++)
                    xq[p][q] = xb[q * Hh + j0 + rj + 4 * p];
        }

        ull acc[8][8];
        #pragma unroll
        for (int j = 0; j < 8; j++)
            #pragma unroll
            for (int r = 0; r < 8; r++) acc[j][r] = 0ull;

        #pragma unroll
        for (int u = 0; u < 8; u++) {
            int idx = u * 256 + tid;
            int b = idx >> 5, k4 = idx & 31;
            float4 v = *(const float4*)(hcur + b * Hh + k4 * 4);
            F2 t0, t1; t0.f = make_float2(v.x, v.y); t1.f = make_float2(v.z, v.w);
            ulonglong2 w2; w2.x = t0.u; w2.y = t1.u;
            *(ulonglong2*)(hd + b * HDR + k4 * 2) = w2;
        }
        __syncthreads();

        int buf = 0;
        for (int ch = 0; ch < 8; ch++) {
            if (ch < 7) {
                int nb = buf ^ 1;
                const float* hsrc = hcur + (ch + 1) * 128;
                #pragma unroll
                for (int u = 0; u < 8; u++) {
                    int idx = u * 256 + tid;
                    int b = idx >> 5, k4 = idx & 31;
                    float4 v = *(const float4*)(hsrc + b * Hh + k4 * 4);
                    F2 t0, t1; t0.f = make_float2(v.x, v.y); t1.f = make_float2(v.z, v.w);
                    ulonglong2 w2; w2.x = t0.u; w2.y = t1.u;
                    *(ulonglong2*)(hd + (nb * 64 + b) * HDR + k4 * 2) = w2;
                }
            }
            const ull* hb = hd + (size_t)buf * 64 * HDR + bg * 8 * HDR;
            const ull* wb = ws + (size_t)(ch * 64) * WSR + rg * 8;
            #pragma unroll
            for (int i = 0; i < 8; i++) {
                const int kl = i * 8 + sl;
                ulonglong2 wA = *(const ulonglong2*)(wb + kl * WSR);
                ulonglong2 wB = *(const ulonglong2*)(wb + kl * WSR + 2);
                ulonglong2 wC = *(const ulonglong2*)(wb + kl * WSR + 4);
                ulonglong2 wD = *(const ulonglong2*)(wb + kl * WSR + 6);
                ull hv[8];
                #pragma unroll
                for (int j = 0; j < 8; j++) hv[j] = hb[j * HDR + kl];
                #pragma unroll
                for (int j = 0; j < 8; j++) {
                    FMA2(acc[j][0], hv[j], wA.x); FMA2(acc[j][1], hv[j], wA.y);
                    FMA2(acc[j][2], hv[j], wB.x); FMA2(acc[j][3], hv[j], wB.y);
                    FMA2(acc[j][4], hv[j], wC.x); FMA2(acc[j][5], hv[j], wC.y);
                    FMA2(acc[j][6], hv[j], wD.x); FMA2(acc[j][7], hv[j], wD.y);
                }
            }
            __syncthreads();
            buf ^= 1;
        }

        #pragma unroll
        for (int j = 0; j < 8; j++)
            #pragma unroll
            for (int r = 0; r < 8; r++) {
                F2 u; u.u = acc[j][r];
                float v = u.f.x + u.f.y;
                v += __shfl_xor_sync(0xffffffffu, v, 1);
                v += __shfl_xor_sync(0xffffffffu, v, 2);
                v += __shfl_xor_sync(0xffffffffu, v, 4);
                if (sl == 0) gb[(bg * 8 + j) * 33 + rg * 8 + r] = v;
            }
        __syncthreads();

        #pragma unroll
        for (int p = 0; p < 2; p++) {
            const int jj = rj + 4 * p;
            const float* gr = gb + rb * 33;
            float gi = gr[jj]      + xq[p][0];
            float gf = gr[8 + jj]  + xq[p][1];
            float gg = gr[16 + jj] + xq[p][2];
            float go = gr[24 + jj] + xq[p][3];
            float iv = sigf(gi), fv = sigf(gf), ov = sigf(go);
            float gv = 2.0f * sigf(2.0f * gg) - 1.0f;
            float cc = (p ? cr1 : cr0);
            cc = fv * cc + iv * gv;
            if (p) cr1 = cc; else cr0 = cc;
            float hv = ov * (2.0f * sigf(2.0f * cc) - 1.0f);
            hnxt[rb * Hh + j0 + jj] = hv;
            out[((size_t)rb * Tt + t) * Hh + j0 + jj] = hv;
            if (t == Tt - 1) {
                out[HSEQ_N + rb * Hh + j0 + jj] = hv;
                out[HSEQ_N + Bb * Hh + rb * Hh + j0 + jj] = cc;
            }
        }

        if (t < Tt - 1) {
            __syncthreads();
            if (tid == 0) {
                __threadfence();
                unsigned g = *(volatile unsigned*)&g_bar_gen;
                if (atomicAdd(&g_bar_count, 1u) == gridDim.x - 1u) {
                    atomicExch(&g_bar_count, 0u);
                    __threadfence();
                    atomicAdd(&g_bar_gen, 1u);
                } else {
                    while (*(volatile unsigned*)&g_bar_gen == g) __nanosleep(64);
                }
                __threadfence();
            }
            __syncthreads();
        }
    }
}

// ===========================================================================
extern "C" void kernel_launch(void* const* d_in, const int* in_sizes, int n_in,
                              void* d_out, int out_size)
{
    (void)in_sizes; (void)n_in; (void)out_size;
    const float* x   = (const float*)d_in[0];
    const float* h0  = (const float*)d_in[1];
    const float* c0  = (const float*)d_in[2];
    const float* Wii = (const float*)d_in[3];
    const float* Whi = (const float*)d_in[4];
    const float* bi  = (const float*)d_in[5];
    const float* Wif = (const float*)d_in[6];
    const float* Whf = (const float*)d_in[7];
    const float* bf  = (const float*)d_in[8];
    const float* Wig = (const float*)d_in[9];
    const float* Whg = (const float*)d_in[10];
    const float* bg_ = (const float*)d_in[11];
    const float* Wio = (const float*)d_in[12];
    const float* Who = (const float*)d_in[13];
    const float* bo  = (const float*)d_in[14];
    float* out = (float*)d_out;

    conv_a_kernel<<<65536, 256>>>(x);                   // A' bf16 split
    conv_w_kernel<<<8192, 256>>>(Wii, Wif, Wig, Wio);   // W' bf16 split
    gemm_mma<<<8192, 256>>>(bi, bf, bg_, bo);           // x_proj via HMMA

    static int attr_done = 0;
    if (!attr_done) {
        cudaFuncSetAttribute(lstm_scan,
                             cudaFuncAttributeMaxDynamicSharedMemorySize, SM_SCAN);
        attr_done = 1;
    }
    lstm_scan<<<128, 256, SM_SCAN>>>(h0, c0, Whi, Whf, Whg, Who, out);
}

// round 13
// speedup vs baseline: 2.7166x; 1.1848x over previous
#include <cuda_runtime.h>
#include <cuda_bf16.h>
#include <cstdint>

typedef unsigned long long ull;
union F2 { float2 f; ull u; };

#define Bb 64
#define Tt 512
#define Hh 1024
#define G4 4096
#define KE 3072
#define HSEQ_N (Bb*Tt*Hh)

// scratch (device globals: allocation-free rule)
__device__ float g_xp[(size_t)Bb * Tt * G4];          // 512 MB x_proj
__device__ __nv_bfloat16 g_abf[(size_t)Bb * Tt * KE]; // 192 MB  A' = [hi, lo, hi]
__device__ __nv_bfloat16 g_wbf[(size_t)G4 * KE];      // 24 MB   W' = [hi, hi, lo]
__device__ __nv_bfloat16 g_hh[2][Bb * Hh];            // h hi, double-buffered
__device__ __nv_bfloat16 g_hl[2][Bb * Hh];            // h lo
__device__ unsigned g_bar_count;
__device__ unsigned g_bar_gen;

__device__ __forceinline__ uint32_t smem_u32(const void* p) {
    uint32_t a;
    asm("{ .reg .u64 t; cvta.to.shared.u64 t, %1; cvt.u32.u64 %0, t; }" : "=r"(a) : "l"(p));
    return a;
}

#define LDMX4(r0,r1,r2,r3,addr) \
    asm volatile("ldmatrix.sync.aligned.m8n8.x4.shared.b16 {%0,%1,%2,%3}, [%4];" \
        : "=r"(r0), "=r"(r1), "=r"(r2), "=r"(r3) : "r"(addr))

#define MMA16816(d,a0,a1,a2,a3,b0,b1) \
    asm volatile("mma.sync.aligned.m16n8k16.row.col.f32.bf16.bf16.f32 " \
        "{%0,%1,%2,%3}, {%4,%5,%6,%7}, {%8,%9}, {%0,%1,%2,%3};" \
        : "+f"((d)[0]), "+f"((d)[1]), "+f"((d)[2]), "+f"((d)[3]) \
        : "r"(a0), "r"(a1), "r"(a2), "r"(a3), "r"(b0), "r"(b1))

__device__ __forceinline__ float sigf(float x) { return 1.0f / (1.0f + __expf(-x)); }

// ---------------------------------------------------------------------------
// bf16-split conversions
// ---------------------------------------------------------------------------
__global__ __launch_bounds__(256) void conv_a_kernel(const float* __restrict__ x)
{
    size_t base = ((size_t)blockIdx.x * 256 + threadIdx.x) * 2;
    int m = (int)(base >> 10), k = (int)(base & 1023);
    float2 a = *(const float2*)(x + base);
    __nv_bfloat16 h0 = __float2bfloat16(a.x);
    __nv_bfloat16 h1 = __float2bfloat16(a.y);
    __nv_bfloat16 l0 = __float2bfloat16(a.x - __bfloat162float(h0));
    __nv_bfloat16 l1 = __float2bfloat16(a.y - __bfloat162float(h1));
    __nv_bfloat162 hh; hh.x = h0; hh.y = h1;
    __nv_bfloat162 ll; ll.x = l0; ll.y = l1;
    __nv_bfloat16* dst = g_abf + (size_t)m * KE + k;
    *(__nv_bfloat162*)(dst)        = hh;
    *(__nv_bfloat162*)(dst + 1024) = ll;
    *(__nv_bfloat162*)(dst + 2048) = hh;
}

__global__ __launch_bounds__(256) void conv_w_kernel(
    const float* __restrict__ W0, const float* __restrict__ W1,
    const float* __restrict__ W2, const float* __restrict__ W3)
{
    size_t base = ((size_t)blockIdx.x * 256 + threadIdx.x) * 2;
    int n = (int)(base >> 10), k = (int)(base & 1023);
    int q = n >> 10;
    const float* W = (q == 0) ? W0 : (q == 1) ? W1 : (q == 2) ? W2 : W3;
    float2 a = *(const float2*)(W + (size_t)(n & 1023) * 1024 + k);
    __nv_bfloat16 h0 = __float2bfloat16(a.x);
    __nv_bfloat16 h1 = __float2bfloat16(a.y);
    __nv_bfloat16 l0 = __float2bfloat16(a.x - __bfloat162float(h0));
    __nv_bfloat16 l1 = __float2bfloat16(a.y - __bfloat162float(h1));
    __nv_bfloat162 hh; hh.x = h0; hh.y = h1;
    __nv_bfloat162 ll; ll.x = l0; ll.y = l1;
    __nv_bfloat16* dst = g_wbf + (size_t)n * KE + k;
    *(__nv_bfloat162*)(dst)        = hh;
    *(__nv_bfloat162*)(dst + 1024) = hh;
    *(__nv_bfloat162*)(dst + 2048) = ll;
}

__global__ __launch_bounds__(256) void conv_h0_kernel(const float* __restrict__ h0)
{
    int i = blockIdx.x * 256 + threadIdx.x;     // 65536 elems
    float v = h0[i];
    __nv_bfloat16 h = __float2bfloat16(v);
    g_hh[0][i] = h;
    g_hl[0][i] = __float2bfloat16(v - __bfloat162float(h));
}

// ---------------------------------------------------------------------------
// mma.sync bf16 GEMM for x_proj (validated in R11)
// ---------------------------------------------------------------------------
__global__ __launch_bounds__(256) void gemm_mma(
    const float* __restrict__ b0, const float* __restrict__ b1,
    const float* __restrict__ b2, const float* __restrict__ b3)
{
    __shared__ __align__(128) char smA[2][8192];
    __shared__ __align__(128) char smB[2][8192];

    const int tid = threadIdx.x, wid = tid >> 5, lane = tid & 31;
    const int mTile = blockIdx.x >> 5, nTile = blockIdx.x & 31;
    const int m0 = mTile * 128, n0 = nTile * 128;
    const int m_w = (wid & 3) * 32;
    const int n_wb = (wid >> 2) * 64;

    const uint32_t sA = smem_u32(smA);
    const uint32_t sB = smem_u32(smB);

    const int r0i = tid >> 2, s0 = tid & 3;
    const int r1i = (tid + 256) >> 2, s1 = (tid + 256) & 3;
    const uint32_t st0 = (uint32_t)((r0i >> 1) * 128 + ((((r0i & 1) * 4 + s0) ^ ((r0i >> 1) & 7)) * 16));
    const uint32_t st1 = (uint32_t)((r1i >> 1) * 128 + ((((r1i & 1) * 4 + s1) ^ ((r1i >> 1) & 7)) * 16));
    const __nv_bfloat16* gA0 = g_abf + (size_t)(m0 + r0i) * KE + s0 * 8;
    const __nv_bfloat16* gA1 = g_abf + (size_t)(m0 + r1i) * KE + s1 * 8;
    const __nv_bfloat16* gB0 = g_wbf + (size_t)(n0 + r0i) * KE + s0 * 8;
    const __nv_bfloat16* gB1 = g_wbf + (size_t)(n0 + r1i) * KE + s1 * 8;

    const int row_l = lane & 15, sh = lane >> 4;
    uint32_t offA[2], offB[4];
    #pragma unroll
    for (int a = 0; a < 2; a++) {
        int r = m_w + a * 16 + row_l;
        int L = r >> 1, p = (r & 1) * 4 + sh;
        offA[a] = (uint32_t)(L * 128 + ((p ^ (L & 7)) * 16));
    }
    #pragma unroll
    for (int b = 0; b < 4; b++) {
        int r = n_wb + b * 16 + row_l;
        int L = r >> 1, p = (r & 1) * 4 + sh;
        offB[b] = (uint32_t)(L * 128 + ((p ^ (L & 7)) * 16));
    }

    float acc[2][8][4];
    #pragma unroll
    for (int a = 0; a < 2; a++)
        #pragma unroll
        for (int n = 0; n < 8; n++)
            #pragma unroll
            for (int c = 0; c < 4; c++) acc[a][n][c] = 0.0f;

    *(uint4*)(smA[0] + st0) = *(const uint4*)(gA0);
    *(uint4*)(smA[0] + st1) = *(const uint4*)(gA1);
    *(uint4*)(smB[0] + st0) = *(const uint4*)(gB0);
    *(uint4*)(smB[0] + st1) = *(const uint4*)(gB1);
    __syncthreads();

    int buf = 0;
    for (int ch = 0; ch < 96; ch++) {
        if (ch < 95) {
            const int nb = buf ^ 1;
            const int ko = (ch + 1) * 32;
            *(uint4*)(smA[nb] + st0) = *(const uint4*)(gA0 + ko);
            *(uint4*)(smA[nb] + st1) = *(const uint4*)(gA1 + ko);
            *(uint4*)(smB[nb] + st0) = *(const uint4*)(gB0 + ko);
            *(uint4*)(smB[nb] + st1) = *(const uint4*)(gB1 + ko);
        }
        const uint32_t bA = sA + buf * 8192;
        const uint32_t bB = sB + buf * 8192;
        #pragma unroll
        for (int ks = 0; ks < 2; ks++) {
            const uint32_t kx = ks * 32;
            uint32_t af[2][4], bf_[4][4];
            #pragma unroll
            for (int a = 0; a < 2; a++)
                LDMX4(af[a][0], af[a][1], af[a][2], af[a][3], (bA + offA[a]) ^ kx);
            #pragma unroll
            for (int b = 0; b < 4; b++)
                LDMX4(bf_[b][0], bf_[b][1], bf_[b][2], bf_[b][3], (bB + offB[b]) ^ kx);
            #pragma unroll
            for (int a = 0; a < 2; a++)
                #pragma unroll
                for (int nt = 0; nt < 8; nt++) {
                    const int bt = nt >> 1, hl = nt & 1;
                    MMA16816(acc[a][nt], af[a][0], af[a][1], af[a][2], af[a][3],
                             bf_[bt][hl], bf_[bt][hl + 2]);
                }
        }
        __syncthreads();
        buf ^= 1;
    }

    const int q = n0 >> 10;
    const float* bp = (q == 0) ? b0 : (q == 1) ? b1 : (q == 2) ? b2 : b3;
    const int nqb = (n0 & 1023) + n_wb;
    #pragma unroll
    for (int a = 0; a < 2; a++) {
        const int row0 = m0 + m_w + a * 16 + (lane >> 2);
        #pragma unroll
        for (int nt = 0; nt < 8; nt++) {
            const int col = n_wb + nt * 8 + (lane & 3) * 2;
            const float bv0 = __ldg(bp + nqb + nt * 8 + (lane & 3) * 2);
            const float bv1 = __ldg(bp + nqb + nt * 8 + (lane & 3) * 2 + 1);
            float2 v0 = make_float2(acc[a][nt][0] + bv0, acc[a][nt][1] + bv1);
            float2 v1 = make_float2(acc[a][nt][2] + bv0, acc[a][nt][3] + bv1);
            *(float2*)(g_xp + (size_t)row0 * G4 + n0 + col)       = v0;
            *(float2*)(g_xp + (size_t)(row0 + 8) * G4 + n0 + col) = v1;
        }
    }
}

// ===========================================================================
// Phase 2: persistent tensor-core scan. 128 CTAs x 256 thr (8 warps).
// CTA: 32 gate rows (8 hidden x 4 gates). Wh hi/lo SMEM-resident swizzled
// (128 KB, loaded once). Per step: gates[64,32] = hhi@Whi + hlo@Whi + hhi@Wlo
// via m16n8k16 MMAs; h chunks (32 k) double-buffered from global bf16.
// Warp (8): m_w=(wid&3)*16 batches, n_w=(wid>>2)*16 rows; 16x16 block each.
// ===========================================================================
#define SMS_WH 65536
#define SMS_HS 16384
#define SM_SCAN2 (2*SMS_WH + SMS_HS + 64*34*4)   // 156160

__global__ __launch_bounds__(256, 1) void lstm_scan_mma(
    const float* __restrict__ c0,
    const float* __restrict__ Whi, const float* __restrict__ Whf,
    const float* __restrict__ Whg, const float* __restrict__ Who,
    float* __restrict__ out)
{
    extern __shared__ char sm[];
    char* whh = sm;                      // Wh_hi: 32 chunks x 2048 B
    char* whl = sm + SMS_WH;             // Wh_lo
    char* hs  = sm + 2 * SMS_WH;         // h stage: [2 buf][hi 4K | lo 4K]
    float* gb = (float*)(sm + 2 * SMS_WH + SMS_HS);   // [64][34]

    const int tid = threadIdx.x, wid = tid >> 5, lane = tid & 31;
    const int j0 = blockIdx.x * 8;

    // ---- one-time: Wh -> smem swizzled bf16 hi/lo ----
    const float* Wm[4] = {Whi, Whf, Whg, Who};
    {
        const int r = tid >> 3;          // 0..31
        const int kt = tid & 7;          // k window kt*128..+127
        const float* src = Wm[r >> 3] + (size_t)(j0 + (r & 7)) * Hh + kt * 128;
        const int L = r >> 1, rb4 = (r & 1) * 4, Lx = L & 7;
        for (int kk = 0; kk < 128; kk += 4) {
            const int k = kt * 128 + kk;
            float4 v = *(const float4*)(src + kk);
            union { __nv_bfloat16 b[4]; ull u; } uh, ul;
            #pragma unroll
            for (int e = 0; e < 4; e++) {
                float f = (&v.x)[e];
                uh.b[e] = __float2bfloat16(f);
                ul.b[e] = __float2bfloat16(f - __bfloat162float(uh.b[e]));
            }
            const int c = k >> 5, s = (k & 31) >> 3, e0 = k & 7;
            const int addr = c * 2048 + L * 128 + (((rb4 + s) ^ Lx) * 16) + e0 * 2;
            *(ull*)(whh + addr) = uh.u;
            *(ull*)(whl + addr) = ul.u;
        }
    }

    // ldmatrix offsets (validated formulas from gemm_mma)
    const int row_l = lane & 15, sh = lane >> 4;
    const int m_w = (wid & 3) * 16, n_w = (wid >> 2) * 16;
    uint32_t offA, offB;
    {
        int r = m_w + row_l;
        int L = r >> 1, p = (r & 1) * 4 + sh;
        offA = (uint32_t)(L * 128 + ((p ^ (L & 7)) * 16));
        r = n_w + row_l;
        L = r >> 1; p = (r & 1) * 4 + sh;
        offB = (uint32_t)(L * 128 + ((p ^ (L & 7)) * 16));
    }
    const uint32_t hsu = smem_u32(hs);
    const uint32_t whhu = smem_u32(whh);
    const uint32_t whlu = smem_u32(whl);

    // h staging mapping: thread -> (batch sb, 16B seg ss)
    const int sb = tid >> 2, ss = tid & 3;
    const uint32_t stg = (uint32_t)((sb >> 1) * 128 + ((((sb & 1) * 4 + ss) ^ ((sb >> 1) & 7)) * 16));
    const size_t gsb = (size_t)sb * Hh + ss * 8;

    // gate cells: 2 per thread
    const int grb = tid >> 2, grj = tid & 3;
    float cr0 = c0[grb * Hh + j0 + grj];
    float cr1 = c0[grb * Hh + j0 + grj + 4];
    __syncthreads();

    for (int t = 0; t < Tt; t++) {
        const int cur = t & 1, nxt = cur ^ 1;
        const __nv_bfloat16* hhp = g_hh[cur];
        const __nv_bfloat16* hlp = g_hl[cur];

        // prefetch x_proj contributions
        float xq[2][4];
        {
            const float* xb = g_xp + ((size_t)grb * Tt + t) * G4;
            #pragma unroll
            for (int p = 0; p < 2; p++)
                #pragma unroll
                for (int q = 0; q < 4; q++)
                    xq[p][q] = xb[q * Hh + j0 + grj + 4 * p];
        }

        float acc[3][2][4];
        #pragma unroll
        for (int tm = 0; tm < 3; tm++)
            #pragma unroll
            for (int n8 = 0; n8 < 2; n8++)
                #pragma unroll
                for (int c = 0; c < 4; c++) acc[tm][n8][c] = 0.0f;

        // stage chunk 0
        *(uint4*)(hs + stg)        = *(const uint4*)(hhp + gsb);
        *(uint4*)(hs + 4096 + stg) = *(const uint4*)(hlp + gsb);
        __syncthreads();

        int buf = 0;
        for (int ch = 0; ch < 32; ch++) {
            uint4 ph, pl;
            const bool has = (ch < 31);
            if (has) {                       // LDG next chunk early
                ph = *(const uint4*)(hhp + gsb + (ch + 1) * 32);
                pl = *(const uint4*)(hlp + gsb + (ch + 1) * 32);
            }
            const uint32_t bA = hsu + buf * 8192;
            const uint32_t wHc = whhu + ch * 2048;
            const uint32_t wLc = whlu + ch * 2048;
            #pragma unroll
            for (int ks = 0; ks < 2; ks++) {
                const uint32_t kx = ks * 32;
                uint32_t ah[4], al[4], bh[4], bl[4];
                LDMX4(ah[0], ah[1], ah[2], ah[3], (bA + offA) ^ kx);
                LDMX4(al[0], al[1], al[2], al[3], (bA + 4096 + offA) ^ kx);
                LDMX4(bh[0], bh[1], bh[2], bh[3], (wHc + offB) ^ kx);
                LDMX4(bl[0], bl[1], bl[2], bl[3], (wLc + offB) ^ kx);
                MMA16816(acc[0][0], ah[0], ah[1], ah[2], ah[3], bh[0], bh[2]);
                MMA16816(acc[0][1], ah[0], ah[1], ah[2], ah[3], bh[1], bh[3]);
                MMA16816(acc[1][0], al[0], al[1], al[2], al[3], bh[0], bh[2]);
                MMA16816(acc[1][1], al[0], al[1], al[2], al[3], bh[1], bh[3]);
                MMA16816(acc[2][0], ah[0], ah[1], ah[2], ah[3], bl[0], bl[2]);
                MMA16816(acc[2][1], ah[0], ah[1], ah[2], ah[3], bl[1], bl[3]);
            }
            if (has) {                       // STS next chunk after compute
                const int nb = buf ^ 1;
                *(uint4*)(hs + nb * 8192 + stg)        = ph;
                *(uint4*)(hs + nb * 8192 + 4096 + stg) = pl;
            }
            __syncthreads();
            buf ^= 1;
        }

        // sum 3 terms, store warp block to gb
        {
            const int erow = m_w + (lane >> 2);
            const int ecol = n_w + (lane & 3) * 2;
            #pragma unroll
            for (int n8 = 0; n8 < 2; n8++) {
                float v0 = acc[0][n8][0] + acc[1][n8][0] + acc[2][n8][0];
                float v1 = acc[0][n8][1] + acc[1][n8][1] + acc[2][n8][1];
                float v2 = acc[0][n8][2] + acc[1][n8][2] + acc[2][n8][2];
                float v3 = acc[0][n8][3] + acc[1][n8][3] + acc[2][n8][3];
                float* q0 = gb + erow * 34 + ecol + n8 * 8;
                q0[0] = v0; q0[1] = v1;
                float* q1 = gb + (erow + 8) * 34 + ecol + n8 * 8;
                q1[0] = v2; q1[1] = v3;
            }
        }
        __syncthreads();

        // gates + state update + h hi/lo store
        #pragma unroll
        for (int p = 0; p < 2; p++) {
            const int jj = grj + 4 * p;
            const float* gr = gb + grb * 34;
            float gi = gr[jj]      + xq[p][0];
            float gf = gr[8 + jj]  + xq[p][1];
            float gg = gr[16 + jj] + xq[p][2];
            float go = gr[24 + jj] + xq[p][3];
            float iv = sigf(gi), fv = sigf(gf), ov = sigf(go);
            float gv = 2.0f * sigf(2.0f * gg) - 1.0f;
            float cc = (p ? cr1 : cr0);
            cc = fv * cc + iv * gv;
            if (p) cr1 = cc; else cr0 = cc;
            float hv = ov * (2.0f * sigf(2.0f * cc) - 1.0f);
            const size_t hidx = (size_t)grb * Hh + j0 + jj;
            __nv_bfloat16 hb_ = __float2bfloat16(hv);
            g_hh[nxt][hidx] = hb_;
            g_hl[nxt][hidx] = __float2bfloat16(hv - __bfloat162float(hb_));
            out[((size_t)grb * Tt + t) * Hh + j0 + jj] = hv;
            if (t == Tt - 1) {
                out[HSEQ_N + hidx] = hv;
                out[HSEQ_N + Bb * Hh + hidx] = cc;
            }
        }

        if (t < Tt - 1) {                    // grid barrier
            __syncthreads();
            if (tid == 0) {
                __threadfence();
                unsigned g = *(volatile unsigned*)&g_bar_gen;
                if (atomicAdd(&g_bar_count, 1u) == gridDim.x - 1u) {
                    atomicExch(&g_bar_count, 0u);
                    __threadfence();
                    atomicAdd(&g_bar_gen, 1u);
                } else {
                    while (*(volatile unsigned*)&g_bar_gen == g) __nanosleep(64);
                }
                __threadfence();
            }
            __syncthreads();
        }
    }
}

// ===========================================================================
extern "C" void kernel_launch(void* const* d_in, const int* in_sizes, int n_in,
                              void* d_out, int out_size)
{
    (void)in_sizes; (void)n_in; (void)out_size;
    const float* x   = (const float*)d_in[0];
    const float* h0  = (const float*)d_in[1];
    const float* c0  = (const float*)d_in[2];
    const float* Wii = (const float*)d_in[3];
    const float* Whi = (const float*)d_in[4];
    const float* bi  = (const float*)d_in[5];
    const float* Wif = (const float*)d_in[6];
    const float* Whf = (const float*)d_in[7];
    const float* bf  = (const float*)d_in[8];
    const float* Wig = (const float*)d_in[9];
    const float* Whg = (const float*)d_in[10];
    const float* bg_ = (const float*)d_in[11];
    const float* Wio = (const float*)d_in[12];
    const float* Who = (const float*)d_in[13];
    const float* bo  = (const float*)d_in[14];
    float* out = (float*)d_out;

    conv_a_kernel<<<65536, 256>>>(x);                   // A' bf16 split
    conv_w_kernel<<<8192, 256>>>(Wii, Wif, Wig, Wio);   // W' bf16 split
    conv_h0_kernel<<<256, 256>>>(h0);                   // h0 hi/lo
    gemm_mma<<<8192, 256>>>(bi, bf, bg_, bo);           // x_proj via HMMA

    static int attr_done = 0;
    if (!attr_done) {
        cudaFuncSetAttribute(lstm_scan_mma,
                             cudaFuncAttributeMaxDynamicSharedMemorySize, SM_SCAN2);
        attr_done = 1;
    }
    lstm_scan_mma<<<128, 256, SM_SCAN2>>>(c0, Whi, Whf, Whg, Who, out);
}

// round 14
// speedup vs baseline: 3.6233x; 1.3338x over previous
#include <cuda_runtime.h>
#include <cuda_bf16.h>
#include <cstdint>

typedef unsigned long long ull;
union F2 { float2 f; ull u; };

#define Bb 64
#define Tt 512
#define Hh 1024
#define G4 4096
#define KE 3072
#define HSEQ_N (Bb*Tt*Hh)

// scratch (device globals: allocation-free rule)
__device__ float g_xp[(size_t)Bb * Tt * G4];          // 512 MB x_proj
__device__ __nv_bfloat16 g_abf[(size_t)Bb * Tt * KE]; // 192 MB  A' = [hi, lo, hi]
__device__ __nv_bfloat16 g_wbf[(size_t)G4 * KE];      // 24 MB   W' = [hi, hi, lo]
__device__ __nv_bfloat16 g_hh[2][Bb * Hh];            // h hi, double-buffered
__device__ __nv_bfloat16 g_hl[2][Bb * Hh];            // h lo
__device__ unsigned g_bar_count;
__device__ unsigned g_bar_gen;

__device__ __forceinline__ uint32_t smem_u32(const void* p) {
    uint32_t a;
    asm("{ .reg .u64 t; cvta.to.shared.u64 t, %1; cvt.u32.u64 %0, t; }" : "=r"(a) : "l"(p));
    return a;
}

#define LDMX4(r0,r1,r2,r3,addr) \
    asm volatile("ldmatrix.sync.aligned.m8n8.x4.shared.b16 {%0,%1,%2,%3}, [%4];" \
        : "=r"(r0), "=r"(r1), "=r"(r2), "=r"(r3) : "r"(addr))

#define MMA16816(d,a0,a1,a2,a3,b0,b1) \
    asm volatile("mma.sync.aligned.m16n8k16.row.col.f32.bf16.bf16.f32 " \
        "{%0,%1,%2,%3}, {%4,%5,%6,%7}, {%8,%9}, {%0,%1,%2,%3};" \
        : "+f"((d)[0]), "+f"((d)[1]), "+f"((d)[2]), "+f"((d)[3]) \
        : "r"(a0), "r"(a1), "r"(a2), "r"(a3), "r"(b0), "r"(b1))

__device__ __forceinline__ float sigf(float x) { return 1.0f / (1.0f + __expf(-x)); }

// ---------------------------------------------------------------------------
// bf16-split conversions
// ---------------------------------------------------------------------------
__global__ __launch_bounds__(256) void conv_a_kernel(const float* __restrict__ x)
{
    size_t base = ((size_t)blockIdx.x * 256 + threadIdx.x) * 2;
    int m = (int)(base >> 10), k = (int)(base & 1023);
    float2 a = *(const float2*)(x + base);
    __nv_bfloat16 h0 = __float2bfloat16(a.x);
    __nv_bfloat16 h1 = __float2bfloat16(a.y);
    __nv_bfloat16 l0 = __float2bfloat16(a.x - __bfloat162float(h0));
    __nv_bfloat16 l1 = __float2bfloat16(a.y - __bfloat162float(h1));
    __nv_bfloat162 hh; hh.x = h0; hh.y = h1;
    __nv_bfloat162 ll; ll.x = l0; ll.y = l1;
    __nv_bfloat16* dst = g_abf + (size_t)m * KE + k;
    *(__nv_bfloat162*)(dst)        = hh;
    *(__nv_bfloat162*)(dst + 1024) = ll;
    *(__nv_bfloat162*)(dst + 2048) = hh;
}

__global__ __launch_bounds__(256) void conv_w_kernel(
    const float* __restrict__ W0, const float* __restrict__ W1,
    const float* __restrict__ W2, const float* __restrict__ W3)
{
    size_t base = ((size_t)blockIdx.x * 256 + threadIdx.x) * 2;
    int n = (int)(base >> 10), k = (int)(base & 1023);
    int q = n >> 10;
    const float* W = (q == 0) ? W0 : (q == 1) ? W1 : (q == 2) ? W2 : W3;
    float2 a = *(const float2*)(W + (size_t)(n & 1023) * 1024 + k);
    __nv_bfloat16 h0 = __float2bfloat16(a.x);
    __nv_bfloat16 h1 = __float2bfloat16(a.y);
    __nv_bfloat16 l0 = __float2bfloat16(a.x - __bfloat162float(h0));
    __nv_bfloat16 l1 = __float2bfloat16(a.y - __bfloat162float(h1));
    __nv_bfloat162 hh; hh.x = h0; hh.y = h1;
    __nv_bfloat162 ll; ll.x = l0; ll.y = l1;
    __nv_bfloat16* dst = g_wbf + (size_t)n * KE + k;
    *(__nv_bfloat162*)(dst)        = hh;
    *(__nv_bfloat162*)(dst + 1024) = hh;
    *(__nv_bfloat162*)(dst + 2048) = ll;
}

__global__ __launch_bounds__(256) void conv_h0_kernel(const float* __restrict__ h0)
{
    int i = blockIdx.x * 256 + threadIdx.x;     // 65536 elems
    float v = h0[i];
    __nv_bfloat16 h = __float2bfloat16(v);
    g_hh[0][i] = h;
    g_hl[0][i] = __float2bfloat16(v - __bfloat162float(h));
}

// ---------------------------------------------------------------------------
// mma.sync bf16 GEMM for x_proj (validated R11) — now forced 2 CTAs/SM
// ---------------------------------------------------------------------------
__global__ __launch_bounds__(256, 2) void gemm_mma(
    const float* __restrict__ b0, const float* __restrict__ b1,
    const float* __restrict__ b2, const float* __restrict__ b3)
{
    __shared__ __align__(128) char smA[2][8192];
    __shared__ __align__(128) char smB[2][8192];

    const int tid = threadIdx.x, wid = tid >> 5, lane = tid & 31;
    const int mTile = blockIdx.x >> 5, nTile = blockIdx.x & 31;
    const int m0 = mTile * 128, n0 = nTile * 128;
    const int m_w = (wid & 3) * 32;
    const int n_wb = (wid >> 2) * 64;

    const uint32_t sA = smem_u32(smA);
    const uint32_t sB = smem_u32(smB);

    const int r0i = tid >> 2, s0 = tid & 3;
    const int r1i = (tid + 256) >> 2, s1 = (tid + 256) & 3;
    const uint32_t st0 = (uint32_t)((r0i >> 1) * 128 + ((((r0i & 1) * 4 + s0) ^ ((r0i >> 1) & 7)) * 16));
    const uint32_t st1 = (uint32_t)((r1i >> 1) * 128 + ((((r1i & 1) * 4 + s1) ^ ((r1i >> 1) & 7)) * 16));
    const __nv_bfloat16* gA0 = g_abf + (size_t)(m0 + r0i) * KE + s0 * 8;
    const __nv_bfloat16* gA1 = g_abf + (size_t)(m0 + r1i) * KE + s1 * 8;
    const __nv_bfloat16* gB0 = g_wbf + (size_t)(n0 + r0i) * KE + s0 * 8;
    const __nv_bfloat16* gB1 = g_wbf + (size_t)(n0 + r1i) * KE + s1 * 8;

    const int row_l = lane & 15, sh = lane >> 4;
    uint32_t offA[2], offB[4];
    #pragma unroll
    for (int a = 0; a < 2; a++) {
        int r = m_w + a * 16 + row_l;
        int L = r >> 1, p = (r & 1) * 4 + sh;
        offA[a] = (uint32_t)(L * 128 + ((p ^ (L & 7)) * 16));
    }
    #pragma unroll
    for (int b = 0; b < 4; b++) {
        int r = n_wb + b * 16 + row_l;
        int L = r >> 1, p = (r & 1) * 4 + sh;
        offB[b] = (uint32_t)(L * 128 + ((p ^ (L & 7)) * 16));
    }

    float acc[2][8][4];
    #pragma unroll
    for (int a = 0; a < 2; a++)
        #pragma unroll
        for (int n = 0; n < 8; n++)
            #pragma unroll
            for (int c = 0; c < 4; c++) acc[a][n][c] = 0.0f;

    *(uint4*)(smA[0] + st0) = *(const uint4*)(gA0);
    *(uint4*)(smA[0] + st1) = *(const uint4*)(gA1);
    *(uint4*)(smB[0] + st0) = *(const uint4*)(gB0);
    *(uint4*)(smB[0] + st1) = *(const uint4*)(gB1);
    __syncthreads();

    int buf = 0;
    for (int ch = 0; ch < 96; ch++) {
        if (ch < 95) {
            const int nb = buf ^ 1;
            const int ko = (ch + 1) * 32;
            *(uint4*)(smA[nb] + st0) = *(const uint4*)(gA0 + ko);
            *(uint4*)(smA[nb] + st1) = *(const uint4*)(gA1 + ko);
            *(uint4*)(smB[nb] + st0) = *(const uint4*)(gB0 + ko);
            *(uint4*)(smB[nb] + st1) = *(const uint4*)(gB1 + ko);
        }
        const uint32_t bA = sA + buf * 8192;
        const uint32_t bB = sB + buf * 8192;
        #pragma unroll
        for (int ks = 0; ks < 2; ks++) {
            const uint32_t kx = ks * 32;
            uint32_t af[2][4], bf_[4][4];
            #pragma unroll
            for (int a = 0; a < 2; a++)
                LDMX4(af[a][0], af[a][1], af[a][2], af[a][3], (bA + offA[a]) ^ kx);
            #pragma unroll
            for (int b = 0; b < 4; b++)
                LDMX4(bf_[b][0], bf_[b][1], bf_[b][2], bf_[b][3], (bB + offB[b]) ^ kx);
            #pragma unroll
            for (int a = 0; a < 2; a++)
                #pragma unroll
                for (int nt = 0; nt < 8; nt++) {
                    const int bt = nt >> 1, hl = nt & 1;
                    MMA16816(acc[a][nt], af[a][0], af[a][1], af[a][2], af[a][3],
                             bf_[bt][hl], bf_[bt][hl + 2]);
                }
        }
        __syncthreads();
        buf ^= 1;
    }

    const int q = n0 >> 10;
    const float* bp = (q == 0) ? b0 : (q == 1) ? b1 : (q == 2) ? b2 : b3;
    const int nqb = (n0 & 1023) + n_wb;
    #pragma unroll
    for (int a = 0; a < 2; a++) {
        const int row0 = m0 + m_w + a * 16 + (lane >> 2);
        #pragma unroll
        for (int nt = 0; nt < 8; nt++) {
            const int col = n_wb + nt * 8 + (lane & 3) * 2;
            const float bv0 = __ldg(bp + nqb + nt * 8 + (lane & 3) * 2);
            const float bv1 = __ldg(bp + nqb + nt * 8 + (lane & 3) * 2 + 1);
            float2 v0 = make_float2(acc[a][nt][0] + bv0, acc[a][nt][1] + bv1);
            float2 v1 = make_float2(acc[a][nt][2] + bv0, acc[a][nt][3] + bv1);
            *(float2*)(g_xp + (size_t)row0 * G4 + n0 + col)       = v0;
            *(float2*)(g_xp + (size_t)(row0 + 8) * G4 + n0 + col) = v1;
        }
    }
}

// ===========================================================================
// Phase 2: persistent tensor-core scan. 128 CTAs x 256 thr (8 warps).
// CHUNK = 128 k's (4 sub-tiles of 32k): 8 syncs/step instead of 32, 96 MMAs
// per warp per chunk to hide the next-chunk LDG latency.
// h stage: [2 buf][hi 16K | lo 16K]; sub-tile sc at sc*4096 (same swizzle).
// Wh hi/lo SMEM-resident (128 KB, loaded once), layout unchanged.
// ===========================================================================
#define SMS_WH 65536
#define SMS_HS 65536
#define SM_SCAN2 (2*SMS_WH + SMS_HS + 64*34*4)   // 205312

__global__ __launch_bounds__(256, 1) void lstm_scan_mma(
    const float* __restrict__ c0,
    const float* __restrict__ Whi, const float* __restrict__ Whf,
    const float* __restrict__ Whg, const float* __restrict__ Who,
    float* __restrict__ out)
{
    extern __shared__ char sm[];
    char* whh = sm;                      // Wh_hi: 32 k-chunks x 2048 B
    char* whl = sm + SMS_WH;             // Wh_lo
    char* hs  = sm + 2 * SMS_WH;         // h stage: [2 buf][hi 16K | lo 16K]
    float* gb = (float*)(sm + 2 * SMS_WH + SMS_HS);   // [64][34]

    const int tid = threadIdx.x, wid = tid >> 5, lane = tid & 31;
    const int j0 = blockIdx.x * 8;

    // ---- one-time: Wh -> smem swizzled bf16 hi/lo ----
    const float* Wm[4] = {Whi, Whf, Whg, Who};
    {
        const int r = tid >> 3;          // 0..31
        const int kt = tid & 7;          // k window kt*128..+127
        const float* src = Wm[r >> 3] + (size_t)(j0 + (r & 7)) * Hh + kt * 128;
        const int L = r >> 1, rb4 = (r & 1) * 4, Lx = L & 7;
        for (int kk = 0; kk < 128; kk += 4) {
            const int k = kt * 128 + kk;
            float4 v = *(const float4*)(src + kk);
            union { __nv_bfloat16 b[4]; ull u; } uh, ul;
            #pragma unroll
            for (int e = 0; e < 4; e++) {
                float f = (&v.x)[e];
                uh.b[e] = __float2bfloat16(f);
                ul.b[e] = __float2bfloat16(f - __bfloat162float(uh.b[e]));
            }
            const int c = k >> 5, s = (k & 31) >> 3, e0 = k & 7;
            const int addr = c * 2048 + L * 128 + (((rb4 + s) ^ Lx) * 16) + e0 * 2;
            *(ull*)(whh + addr) = uh.u;
            *(ull*)(whl + addr) = ul.u;
        }
    }

    // ldmatrix offsets (validated formulas)
    const int row_l = lane & 15, sh = lane >> 4;
    const int m_w = (wid & 3) * 16, n_w = (wid >> 2) * 16;
    uint32_t offA, offB;
    {
        int r = m_w + row_l;
        int L = r >> 1, p = (r & 1) * 4 + sh;
        offA = (uint32_t)(L * 128 + ((p ^ (L & 7)) * 16));
        r = n_w + row_l;
        L = r >> 1; p = (r & 1) * 4 + sh;
        offB = (uint32_t)(L * 128 + ((p ^ (L & 7)) * 16));
    }
    const uint32_t hsu = smem_u32(hs);
    const uint32_t whhu = smem_u32(whh);
    const uint32_t whlu = smem_u32(whl);

    // h staging mapping: thread -> (batch sb, 16B seg ss) per 32k sub-tile
    const int sb = tid >> 2, ss = tid & 3;
    const uint32_t stg = (uint32_t)((sb >> 1) * 128 + ((((sb & 1) * 4 + ss) ^ ((sb >> 1) & 7)) * 16));
    const size_t gsb = (size_t)sb * Hh + ss * 8;

    // gate cells: 2 per thread
    const int grb = tid >> 2, grj = tid & 3;
    float cr0 = c0[grb * Hh + j0 + grj];
    float cr1 = c0[grb * Hh + j0 + grj + 4];
    __syncthreads();

    for (int t = 0; t < Tt; t++) {
        const int cur = t & 1, nxt = cur ^ 1;
        const __nv_bfloat16* hhp = g_hh[cur];
        const __nv_bfloat16* hlp = g_hl[cur];

        // prefetch x_proj contributions
        float xq[2][4];
        {
            const float* xb = g_xp + ((size_t)grb * Tt + t) * G4;
            #pragma unroll
            for (int p = 0; p < 2; p++)
                #pragma unroll
                for (int q = 0; q < 4; q++)
                    xq[p][q] = xb[q * Hh + j0 + grj + 4 * p];
        }

        float acc[3][2][4];
        #pragma unroll
        for (int tm = 0; tm < 3; tm++)
            #pragma unroll
            for (int n8 = 0; n8 < 2; n8++)
                #pragma unroll
                for (int c = 0; c < 4; c++) acc[tm][n8][c] = 0.0f;

        // stage chunk 0 (128 k = 4 sub-tiles)
        #pragma unroll
        for (int sc = 0; sc < 4; sc++) {
            *(uint4*)(hs + sc * 4096 + stg)         = *(const uint4*)(hhp + gsb + sc * 32);
            *(uint4*)(hs + 16384 + sc * 4096 + stg) = *(const uint4*)(hlp + gsb + sc * 32);
        }
        __syncthreads();

        int buf = 0;
        for (int ch = 0; ch < 8; ch++) {
            uint4 ph[4], pl[4];
            const bool has = (ch < 7);
            if (has) {                       // LDG next chunk early
                #pragma unroll
                for (int sc = 0; sc < 4; sc++) {
                    ph[sc] = *(const uint4*)(hhp + gsb + (ch + 1) * 128 + sc * 32);
                    pl[sc] = *(const uint4*)(hlp + gsb + (ch + 1) * 128 + sc * 32);
                }
            }
            const uint32_t bA = hsu + buf * 32768;
            #pragma unroll
            for (int sc = 0; sc < 4; sc++) {
                const uint32_t wHc = whhu + (ch * 4 + sc) * 2048;
                const uint32_t wLc = whlu + (ch * 4 + sc) * 2048;
                const uint32_t aHi = bA + sc * 4096 + offA;
                const uint32_t aLo = bA + 16384 + sc * 4096 + offA;
                #pragma unroll
                for (int ks = 0; ks < 2; ks++) {
                    const uint32_t kx = ks * 32;
                    uint32_t ah[4], al[4], bh[4], bl[4];
                    LDMX4(ah[0], ah[1], ah[2], ah[3], aHi ^ kx);
                    LDMX4(al[0], al[1], al[2], al[3], aLo ^ kx);
                    LDMX4(bh[0], bh[1], bh[2], bh[3], (wHc + offB) ^ kx);
                    LDMX4(bl[0], bl[1], bl[2], bl[3], (wLc + offB) ^ kx);
                    MMA16816(acc[0][0], ah[0], ah[1], ah[2], ah[3], bh[0], bh[2]);
                    MMA16816(acc[0][1], ah[0], ah[1], ah[2], ah[3], bh[1], bh[3]);
                    MMA16816(acc[1][0], al[0], al[1], al[2], al[3], bh[0], bh[2]);
                    MMA16816(acc[1][1], al[0], al[1], al[2], al[3], bh[1], bh[3]);
                    MMA16816(acc[2][0], ah[0], ah[1], ah[2], ah[3], bl[0], bl[2]);
                    MMA16816(acc[2][1], ah[0], ah[1], ah[2], ah[3], bl[1], bl[3]);
                }
            }
            if (has) {                       // STS next chunk after compute
                const int nb = buf ^ 1;
                #pragma unroll
                for (int sc = 0; sc < 4; sc++) {
                    *(uint4*)(hs + nb * 32768 + sc * 4096 + stg)         = ph[sc];
                    *(uint4*)(hs + nb * 32768 + 16384 + sc * 4096 + stg) = pl[sc];
                }
            }
            __syncthreads();
            buf ^= 1;
        }

        // sum 3 terms, store warp block to gb
        {
            const int erow = m_w + (lane >> 2);
            const int ecol = n_w + (lane & 3) * 2;
            #pragma unroll
            for (int n8 = 0; n8 < 2; n8++) {
                float v0 = acc[0][n8][0] + acc[1][n8][0] + acc[2][n8][0];
                float v1 = acc[0][n8][1] + acc[1][n8][1] + acc[2][n8][1];
                float v2 = acc[0][n8][2] + acc[1][n8][2] + acc[2][n8][2];
                float v3 = acc[0][n8][3] + acc[1][n8][3] + acc[2][n8][3];
                float* q0 = gb + erow * 34 + ecol + n8 * 8;
                q0[0] = v0; q0[1] = v1;
                float* q1 = gb + (erow + 8) * 34 + ecol + n8 * 8;
                q1[0] = v2; q1[1] = v3;
            }
        }
        __syncthreads();

        // gates + state update + h hi/lo store
        #pragma unroll
        for (int p = 0; p < 2; p++) {
            const int jj = grj + 4 * p;
            const float* gr = gb + grb * 34;
            float gi = gr[jj]      + xq[p][0];
            float gf = gr[8 + jj]  + xq[p][1];
            float gg = gr[16 + jj] + xq[p][2];
            float go = gr[24 + jj] + xq[p][3];
            float iv = sigf(gi), fv = sigf(gf), ov = sigf(go);
            float gv = 2.0f * sigf(2.0f * gg) - 1.0f;
            float cc = (p ? cr1 : cr0);
            cc = fv * cc + iv * gv;
            if (p) cr1 = cc; else cr0 = cc;
            float hv = ov * (2.0f * sigf(2.0f * cc) - 1.0f);
            const size_t hidx = (size_t)grb * Hh + j0 + jj;
            __nv_bfloat16 hb_ = __float2bfloat16(hv);
            g_hh[nxt][hidx] = hb_;
            g_hl[nxt][hidx] = __float2bfloat16(hv - __bfloat162float(hb_));
            out[((size_t)grb * Tt + t) * Hh + j0 + jj] = hv;
            if (t == Tt - 1) {
                out[HSEQ_N + hidx] = hv;
                out[HSEQ_N + Bb * Hh + hidx] = cc;
            }
        }

        if (t < Tt - 1) {                    // grid barrier
            __syncthreads();
            if (tid == 0) {
                __threadfence();
                unsigned g = *(volatile unsigned*)&g_bar_gen;
                if (atomicAdd(&g_bar_count, 1u) == gridDim.x - 1u) {
                    atomicExch(&g_bar_count, 0u);
                    __threadfence();
                    atomicAdd(&g_bar_gen, 1u);
                } else {
                    while (*(volatile unsigned*)&g_bar_gen == g) __nanosleep(64);
                }
                __threadfence();
            }
            __syncthreads();
        }
    }
}

// ===========================================================================
extern "C" void kernel_launch(void* const* d_in, const int* in_sizes, int n_in,
                              void* d_out, int out_size)
{
    (void)in_sizes; (void)n_in; (void)out_size;
    const float* x   = (const float*)d_in[0];
    const float* h0  = (const float*)d_in[1];
    const float* c0  = (const float*)d_in[2];
    const float* Wii = (const float*)d_in[3];
    const float* Whi = (const float*)d_in[4];
    const float* bi  = (const float*)d_in[5];
    const float* Wif = (const float*)d_in[6];
    const float* Whf = (const float*)d_in[7];
    const float* bf  = (const float*)d_in[8];
    const float* Wig = (const float*)d_in[9];
    const float* Whg = (const float*)d_in[10];
    const float* bg_ = (const float*)d_in[11];
    const float* Wio = (const float*)d_in[12];
    const float* Who = (const float*)d_in[13];
    const float* bo  = (const float*)d_in[14];
    float* out = (float*)d_out;

    conv_a_kernel<<<65536, 256>>>(x);                   // A' bf16 split
    conv_w_kernel<<<8192, 256>>>(Wii, Wif, Wig, Wio);   // W' bf16 split
    conv_h0_kernel<<<256, 256>>>(h0);                   // h0 hi/lo
    gemm_mma<<<8192, 256>>>(bi, bf, bg_, bo);           // x_proj via HMMA

    static int attr_done = 0;
    if (!attr_done) {
        cudaFuncSetAttribute(lstm_scan_mma,
                             cudaFuncAttributeMaxDynamicSharedMemorySize, SM_SCAN2);
        attr_done = 1;
    }
    lstm_scan_mma<<<128, 256, SM_SCAN2>>>(c0, Whi, Whf, Whg, Who, out);
}